// round 1
// baseline (speedup 1.0000x reference)
#include <cuda_runtime.h>
#include <math.h>

// Problem constants (fixed by reference: ADV=8, GOOD=8, BOX=16, RAMP=8)
#define B_SZ   32768
#define HDIM   256
#define OBS    464
#define N_OTHER 15
#define N_BOX   16
#define N_RAMP  8
#define OFF_OTHER 10
#define OFF_BOX   160
#define OFF_RAMP  368

// Scratch (static device globals — allocation-free)
__device__ float g_emb_self[B_SZ * HDIM];          // 33.5 MB
__device__ float g_S[3 * B_SZ * HDIM];             // 100 MB  (emb_self @ corr_g)
__device__ float g_cat[(size_t)B_SZ * 4 * HDIM];   // 134 MB  [gi | vi_other | vi_box | vi_ramp]
__device__ float g_h[B_SZ * HDIM];                 // 33.5 MB

// ---------------------------------------------------------------------------
// Kernel 1: emb_self = tanh(inputs[:, :10] @ W_self + b_self)
// block = 256 threads (one per h), each block handles ROWS_PER_BLOCK rows
// ---------------------------------------------------------------------------
__global__ void self_kernel(const float* __restrict__ inputs,
                            const float* __restrict__ W,
                            const float* __restrict__ b,
                            int rows_per_block) {
    __shared__ float Ws[10 * HDIM];
    __shared__ float bs[HDIM];
    int tid = threadIdx.x;
    for (int i = tid; i < 10 * HDIM; i += blockDim.x) Ws[i] = W[i];
    if (tid < HDIM) bs[tid] = b[tid];
    __syncthreads();

    int row0 = blockIdx.x * rows_per_block;
    for (int r = 0; r < rows_per_block; ++r) {
        int row = row0 + r;
        const float* in = inputs + (size_t)row * OBS;
        float acc = bs[tid];
#pragma unroll
        for (int f = 0; f < 10; ++f) acc += in[f] * Ws[f * HDIM + tid];
        g_emb_self[(size_t)row * HDIM + tid] = tanhf(acc);
    }
}

// ---------------------------------------------------------------------------
// Generic tiled fp32 GEMM: C[m, coff+n] = (tanh?)(A[MxK] @ B[KxN] + bias[n])
// BM=BN=64, BK=16, 256 threads, 4x4 per-thread microtile.
// M % 64 == 0, N % 64 == 0, K % 16 == 0 guaranteed by problem sizes.
// ---------------------------------------------------------------------------
template <bool TANH, bool HAS_BIAS>
__global__ void gemm64(const float* __restrict__ A,
                       const float* __restrict__ Bm,
                       const float* __restrict__ bias,
                       float* __restrict__ C,
                       int K, int N, int ldc, int coff) {
    const int BM = 64, BN = 64, BK = 16;
    __shared__ float As[BM][BK + 1];
    __shared__ float Bs[BK][BN];

    int tid  = threadIdx.x;
    int trow = (tid / 16) * 4;
    int tcol = (tid % 16) * 4;
    int m0 = blockIdx.y * BM;
    int n0 = blockIdx.x * BN;

    float acc[4][4] = {};

    for (int k0 = 0; k0 < K; k0 += BK) {
#pragma unroll
        for (int l = 0; l < 4; ++l) {  // 64x16 A tile
            int idx = tid + l * 256;
            int i = idx / BK, j = idx % BK;
            As[i][j] = A[(size_t)(m0 + i) * K + k0 + j];
        }
#pragma unroll
        for (int l = 0; l < 4; ++l) {  // 16x64 B tile (coalesced)
            int idx = tid + l * 256;
            int i = idx / BN, j = idx % BN;
            Bs[i][j] = Bm[(size_t)(k0 + i) * N + n0 + j];
        }
        __syncthreads();

#pragma unroll
        for (int kk = 0; kk < BK; ++kk) {
            float a[4], bb[4];
#pragma unroll
            for (int i = 0; i < 4; ++i) a[i] = As[trow + i][kk];
#pragma unroll
            for (int j = 0; j < 4; ++j) bb[j] = Bs[kk][tcol + j];
#pragma unroll
            for (int i = 0; i < 4; ++i)
#pragma unroll
                for (int j = 0; j < 4; ++j)
                    acc[i][j] += a[i] * bb[j];
        }
        __syncthreads();
    }

#pragma unroll
    for (int i = 0; i < 4; ++i) {
#pragma unroll
        for (int j = 0; j < 4; ++j) {
            float v = acc[i][j];
            if (HAS_BIAS) v += bias[n0 + tcol + j];
            if (TANH) v = tanhf(v);
            C[(size_t)(m0 + trow + i) * ldc + coff + n0 + tcol + j] = v;
        }
    }
}

// ---------------------------------------------------------------------------
// Kernel 3: fused attention pool per entity group (warp-per-row, online softmax)
// emb_n = tanh(ent_n @ W + b); beta_n = <S_row, emb_n>; vi = softmax(beta)-pool
// Lane owns h = j*32 + lane for j in 0..7.
// ---------------------------------------------------------------------------
template <int NENT, int FDIM, int IN_OFF, int CAT_OFF>
__global__ void attn_kernel(const float* __restrict__ inputs,
                            const float* __restrict__ S,
                            const float* __restrict__ W,
                            const float* __restrict__ b) {
    __shared__ float Ws[FDIM * HDIM];
    __shared__ float bs[HDIM];
    int tid = threadIdx.x;
    for (int i = tid; i < FDIM * HDIM; i += blockDim.x) Ws[i] = W[i];
    for (int i = tid; i < HDIM; i += blockDim.x) bs[i] = b[i];
    __syncthreads();

    int warp = tid >> 5, lane = tid & 31;
    int row = blockIdx.x * 8 + warp;
    if (row >= B_SZ) return;

    float s[8], acc[8];
#pragma unroll
    for (int j = 0; j < 8; ++j) {
        s[j] = S[(size_t)row * HDIM + j * 32 + lane];
        acc[j] = 0.f;
    }
    float m = -INFINITY, l = 0.f;
    const float* rowin = inputs + (size_t)row * OBS + IN_OFF;

    for (int n = 0; n < NENT; ++n) {
        const float* ent = rowin + n * FDIM;
        float feat[FDIM];
#pragma unroll
        for (int f = 0; f < FDIM; ++f) feat[f] = ent[f];  // broadcast loads

        float e[8];
#pragma unroll
        for (int j = 0; j < 8; ++j) {
            int h = j * 32 + lane;
            float a = bs[h];
#pragma unroll
            for (int f = 0; f < FDIM; ++f) a += feat[f] * Ws[f * HDIM + h];
            e[j] = tanhf(a);
        }

        float bp = 0.f;
#pragma unroll
        for (int j = 0; j < 8; ++j) bp += s[j] * e[j];
#pragma unroll
        for (int off = 16; off > 0; off >>= 1)
            bp += __shfl_xor_sync(0xFFFFFFFFu, bp, off);

        // online softmax update
        float mn = fmaxf(m, bp);
        float cr = __expf(m - mn);   // first iter: exp(-inf) = 0
        float w  = __expf(bp - mn);
#pragma unroll
        for (int j = 0; j < 8; ++j) acc[j] = acc[j] * cr + w * e[j];
        l = l * cr + w;
        m = mn;
    }

    float inv = 1.f / l;
#pragma unroll
    for (int j = 0; j < 8; ++j)
        g_cat[(size_t)row * (4 * HDIM) + CAT_OFF + j * 32 + lane] = acc[j] * inv;
}

// ---------------------------------------------------------------------------
extern "C" void kernel_launch(void* const* d_in, const int* in_sizes, int n_in,
                              void* d_out, int out_size) {
    const float* inputs     = (const float*)d_in[0];
    const float* W_self     = (const float*)d_in[1];
    const float* b_self     = (const float*)d_in[2];
    const float* W_other    = (const float*)d_in[3];
    const float* b_other    = (const float*)d_in[4];
    const float* W_box      = (const float*)d_in[5];
    const float* b_box      = (const float*)d_in[6];
    const float* W_ramp     = (const float*)d_in[7];
    const float* b_ramp     = (const float*)d_in[8];
    const float* corr_other = (const float*)d_in[9];
    const float* corr_box   = (const float*)d_in[10];
    const float* corr_ramp  = (const float*)d_in[11];
    const float* W_fc       = (const float*)d_in[12];
    const float* b_fc       = (const float*)d_in[13];
    const float* W_e1       = (const float*)d_in[14];
    const float* b_e1       = (const float*)d_in[15];
    const float* W_e2       = (const float*)d_in[16];
    const float* b_e2       = (const float*)d_in[17];
    float* out = (float*)d_out;

    float *emb_self, *S, *cat, *hbuf;
    cudaGetSymbolAddress((void**)&emb_self, g_emb_self);
    cudaGetSymbolAddress((void**)&S,        g_S);
    cudaGetSymbolAddress((void**)&cat,      g_cat);
    cudaGetSymbolAddress((void**)&hbuf,     g_h);

    const int RPB = 32;
    self_kernel<<<B_SZ / RPB, 256>>>(inputs, W_self, b_self, RPB);

    dim3 g256(HDIM / 64, B_SZ / 64);  // (4, 512)
    // S_g = emb_self @ corr_g   (no bias, no tanh)
    gemm64<false, false><<<g256, 256>>>(emb_self, corr_other, nullptr,
                                        S + 0 * (size_t)B_SZ * HDIM, HDIM, HDIM, HDIM, 0);
    gemm64<false, false><<<g256, 256>>>(emb_self, corr_box, nullptr,
                                        S + 1 * (size_t)B_SZ * HDIM, HDIM, HDIM, HDIM, 0);
    gemm64<false, false><<<g256, 256>>>(emb_self, corr_ramp, nullptr,
                                        S + 2 * (size_t)B_SZ * HDIM, HDIM, HDIM, HDIM, 0);
    // gi = tanh(emb_self @ W_fc + b_fc) -> cat[:, 0:256]
    gemm64<true, true><<<g256, 256>>>(emb_self, W_fc, b_fc,
                                      cat, HDIM, HDIM, 4 * HDIM, 0);

    // attention pools -> cat columns
    attn_kernel<N_OTHER, 10, OFF_OTHER, 1 * HDIM><<<B_SZ / 8, 256>>>(
        inputs, S + 0 * (size_t)B_SZ * HDIM, W_other, b_other);
    attn_kernel<N_BOX, 13, OFF_BOX, 2 * HDIM><<<B_SZ / 8, 256>>>(
        inputs, S + 1 * (size_t)B_SZ * HDIM, W_box, b_box);
    attn_kernel<N_RAMP, 12, OFF_RAMP, 3 * HDIM><<<B_SZ / 8, 256>>>(
        inputs, S + 2 * (size_t)B_SZ * HDIM, W_ramp, b_ramp);

    // h = tanh(cat @ W_e1 + b_e1)
    gemm64<true, true><<<g256, 256>>>(cat, W_e1, b_e1, hbuf, 4 * HDIM, HDIM, HDIM, 0);
    // out = tanh(h @ W_e2 + b_e2)
    gemm64<true, true><<<g256, 256>>>(hbuf, W_e2, b_e2, out, HDIM, HDIM, HDIM, 0);
}

// round 2
// speedup vs baseline: 1.4155x; 1.4155x over previous
#include <cuda_runtime.h>
#include <math.h>

// Problem constants (fixed: ADV=8, GOOD=8, BOX=16, RAMP=8)
#define B_SZ   32768
#define HDIM   256
#define OBS    464
#define N_OTHER 15
#define N_BOX   16
#define N_RAMP  8
#define OFF_OTHER 10
#define OFF_BOX   160
#define OFF_RAMP  368

// Scratch (static device globals — allocation-free)
__device__ float g_emb_self[B_SZ * HDIM];              // 33.5 MB
__device__ float g_S[(size_t)B_SZ * 768];              // 100 MB  [S_other|S_box|S_ramp]
__device__ float g_cat[(size_t)B_SZ * 1024];           // 134 MB  [gi|vi_other|vi_box|vi_ramp]
__device__ float g_h[B_SZ * HDIM];                     // 33.5 MB

__device__ __forceinline__ float fast_tanh(float x) {
    float y;
    asm("tanh.approx.f32 %0, %1;" : "=f"(y) : "f"(x));
    return y;
}

// ---------------------------------------------------------------------------
// Kernel 1: emb_self = tanh(inputs[:, :10] @ W_self + b_self)
// ---------------------------------------------------------------------------
__global__ void self_kernel(const float* __restrict__ inputs,
                            const float* __restrict__ W,
                            const float* __restrict__ b,
                            int rows_per_block) {
    __shared__ float Ws[10 * HDIM];
    __shared__ float bs[HDIM];
    int tid = threadIdx.x;
    for (int i = tid; i < 10 * HDIM; i += blockDim.x) Ws[i] = W[i];
    if (tid < HDIM) bs[tid] = b[tid];
    __syncthreads();

    int row0 = blockIdx.x * rows_per_block;
    for (int r = 0; r < rows_per_block; ++r) {
        int row = row0 + r;
        const float* in = inputs + (size_t)row * OBS;
        float acc = bs[tid];
#pragma unroll
        for (int f = 0; f < 10; ++f) acc += in[f] * Ws[f * HDIM + tid];
        g_emb_self[(size_t)row * HDIM + tid] = fast_tanh(acc);
    }
}

// ---------------------------------------------------------------------------
// SGEMM 128x128x8, 256 threads, 8x8 microtile (split 4+4 rows/cols at +64),
// double-buffered smem, float4 everywhere.
//
// FUSED=true:  B is 4 concatenated [256x256] matrices (B0..B3), N=1024.
//              cols [0,768)  -> raw store to Cs (ldcs)
//              cols [768,1024) -> tanh(v + bias[n-768]) -> Ct (ldct)
// FUSED=false: single B0 with leading dim ldb; all cols -> tanh(v+bias[n]) -> Ct.
// ---------------------------------------------------------------------------
template <bool FUSED>
__global__ __launch_bounds__(256)
void sgemm128(const float* __restrict__ A, int lda, int K,
              const float* __restrict__ B0, const float* __restrict__ B1,
              const float* __restrict__ B2, const float* __restrict__ B3,
              int ldb,
              const float* __restrict__ bias,
              float* __restrict__ Cs, int ldcs,
              float* __restrict__ Ct, int ldct, int tanh_col0) {
    __shared__ float As[2][8][128];
    __shared__ float Bs[2][8][128];

    int tid = threadIdx.x;
    int m0 = blockIdx.y * 128;
    int n0 = blockIdx.x * 128;

    const float* Bp;
    if (FUSED) {
        const float* sel = (n0 < 256) ? B0 : (n0 < 512) ? B1 : (n0 < 768) ? B2 : B3;
        Bp = sel + (n0 & 255);
        ldb = 256;
    } else {
        Bp = B0 + n0;
    }
    const float* Ap = A + (size_t)m0 * lda;

    // loader mapping
    int arow = tid >> 1;            // 0..127
    int acol = (tid & 1) * 4;       // 0 or 4
    int bk   = tid >> 5;            // 0..7
    int bn   = (tid & 31) * 4;      // 0..124

    // compute mapping: rows {tr..tr+3, tr+64..tr+67}, cols {tc..tc+3, tc+64..tc+67}
    int tr = (tid >> 4) * 4;
    int tc = (tid & 15) * 4;

    float4 aR = *(const float4*)(Ap + (size_t)arow * lda + acol);
    float4 bR = *(const float4*)(Bp + (size_t)bk * ldb + bn);
    As[0][acol + 0][arow] = aR.x; As[0][acol + 1][arow] = aR.y;
    As[0][acol + 2][arow] = aR.z; As[0][acol + 3][arow] = aR.w;
    *(float4*)&Bs[0][bk][bn] = bR;
    __syncthreads();

    float acc[8][8] = {};
    int nt = K >> 3;
    for (int t = 0; t < nt; ++t) {
        int cur = t & 1;
        if (t + 1 < nt) {
            aR = *(const float4*)(Ap + (size_t)arow * lda + (t + 1) * 8 + acol);
            bR = *(const float4*)(Bp + (size_t)((t + 1) * 8 + bk) * ldb + bn);
        }
#pragma unroll
        for (int kk = 0; kk < 8; ++kk) {
            float4 a0 = *(const float4*)&As[cur][kk][tr];
            float4 a1 = *(const float4*)&As[cur][kk][tr + 64];
            float4 b0 = *(const float4*)&Bs[cur][kk][tc];
            float4 b1 = *(const float4*)&Bs[cur][kk][tc + 64];
            float av[8] = {a0.x, a0.y, a0.z, a0.w, a1.x, a1.y, a1.z, a1.w};
            float bv[8] = {b0.x, b0.y, b0.z, b0.w, b1.x, b1.y, b1.z, b1.w};
#pragma unroll
            for (int i = 0; i < 8; ++i)
#pragma unroll
                for (int j = 0; j < 8; ++j)
                    acc[i][j] += av[i] * bv[j];
        }
        if (t + 1 < nt) {
            int nx = cur ^ 1;
            As[nx][acol + 0][arow] = aR.x; As[nx][acol + 1][arow] = aR.y;
            As[nx][acol + 2][arow] = aR.z; As[nx][acol + 3][arow] = aR.w;
            *(float4*)&Bs[nx][bk][bn] = bR;
        }
        __syncthreads();
    }

    bool do_tanh = (n0 >= tanh_col0);
#pragma unroll
    for (int i = 0; i < 8; ++i) {
        int row = m0 + ((i < 4) ? (tr + i) : (tr + 64 + i - 4));
        if (do_tanh) {
            int cbase = n0 - tanh_col0;
            float* outp = Ct + (size_t)row * ldct + cbase;
            float4 v0, v1;
            v0.x = fast_tanh(acc[i][0] + bias[cbase + tc + 0]);
            v0.y = fast_tanh(acc[i][1] + bias[cbase + tc + 1]);
            v0.z = fast_tanh(acc[i][2] + bias[cbase + tc + 2]);
            v0.w = fast_tanh(acc[i][3] + bias[cbase + tc + 3]);
            v1.x = fast_tanh(acc[i][4] + bias[cbase + tc + 64]);
            v1.y = fast_tanh(acc[i][5] + bias[cbase + tc + 65]);
            v1.z = fast_tanh(acc[i][6] + bias[cbase + tc + 66]);
            v1.w = fast_tanh(acc[i][7] + bias[cbase + tc + 67]);
            *(float4*)(outp + tc) = v0;
            *(float4*)(outp + tc + 64) = v1;
        } else {
            float* outp = Cs + (size_t)row * ldcs + n0;
            float4 v0 = make_float4(acc[i][0], acc[i][1], acc[i][2], acc[i][3]);
            float4 v1 = make_float4(acc[i][4], acc[i][5], acc[i][6], acc[i][7]);
            *(float4*)(outp + tc) = v0;
            *(float4*)(outp + tc + 64) = v1;
        }
    }
}

// ---------------------------------------------------------------------------
// Fused attention pool per entity group (warp-per-row, online softmax).
// S row stride = 768, group column offset GOFF.
// ---------------------------------------------------------------------------
template <int NENT, int FDIM, int IN_OFF, int GOFF, int CAT_OFF>
__global__ void attn_kernel(const float* __restrict__ inputs,
                            const float* __restrict__ S,
                            const float* __restrict__ W,
                            const float* __restrict__ b) {
    __shared__ float Ws[FDIM * HDIM];
    __shared__ float bs[HDIM];
    int tid = threadIdx.x;
    for (int i = tid; i < FDIM * HDIM; i += blockDim.x) Ws[i] = W[i];
    for (int i = tid; i < HDIM; i += blockDim.x) bs[i] = b[i];
    __syncthreads();

    int warp = tid >> 5, lane = tid & 31;
    int row = blockIdx.x * 8 + warp;
    if (row >= B_SZ) return;

    float s[8], acc[8];
#pragma unroll
    for (int j = 0; j < 8; ++j) {
        s[j] = S[(size_t)row * 768 + GOFF + j * 32 + lane];
        acc[j] = 0.f;
    }
    float m = -INFINITY, l = 0.f;
    const float* rowin = inputs + (size_t)row * OBS + IN_OFF;

    for (int n = 0; n < NENT; ++n) {
        const float* ent = rowin + n * FDIM;
        float feat[FDIM];
#pragma unroll
        for (int f = 0; f < FDIM; ++f) feat[f] = ent[f];  // broadcast loads

        float e[8];
#pragma unroll
        for (int j = 0; j < 8; ++j) {
            int h = j * 32 + lane;
            float a = bs[h];
#pragma unroll
            for (int f = 0; f < FDIM; ++f) a += feat[f] * Ws[f * HDIM + h];
            e[j] = fast_tanh(a);
        }

        float bp = 0.f;
#pragma unroll
        for (int j = 0; j < 8; ++j) bp += s[j] * e[j];
#pragma unroll
        for (int off = 16; off > 0; off >>= 1)
            bp += __shfl_xor_sync(0xFFFFFFFFu, bp, off);

        float mn = fmaxf(m, bp);
        float cr = __expf(m - mn);   // first iter: exp(-inf)=0
        float w  = __expf(bp - mn);
#pragma unroll
        for (int j = 0; j < 8; ++j) acc[j] = acc[j] * cr + w * e[j];
        l = l * cr + w;
        m = mn;
    }

    float inv = 1.f / l;
#pragma unroll
    for (int j = 0; j < 8; ++j)
        g_cat[(size_t)row * 1024 + CAT_OFF + j * 32 + lane] = acc[j] * inv;
}

// ---------------------------------------------------------------------------
extern "C" void kernel_launch(void* const* d_in, const int* in_sizes, int n_in,
                              void* d_out, int out_size) {
    const float* inputs     = (const float*)d_in[0];
    const float* W_self     = (const float*)d_in[1];
    const float* b_self     = (const float*)d_in[2];
    const float* W_other    = (const float*)d_in[3];
    const float* b_other    = (const float*)d_in[4];
    const float* W_box      = (const float*)d_in[5];
    const float* b_box      = (const float*)d_in[6];
    const float* W_ramp     = (const float*)d_in[7];
    const float* b_ramp     = (const float*)d_in[8];
    const float* corr_other = (const float*)d_in[9];
    const float* corr_box   = (const float*)d_in[10];
    const float* corr_ramp  = (const float*)d_in[11];
    const float* W_fc       = (const float*)d_in[12];
    const float* b_fc       = (const float*)d_in[13];
    const float* W_e1       = (const float*)d_in[14];
    const float* b_e1       = (const float*)d_in[15];
    const float* W_e2       = (const float*)d_in[16];
    const float* b_e2       = (const float*)d_in[17];
    float* out = (float*)d_out;

    float *emb_self, *S, *cat, *hbuf;
    cudaGetSymbolAddress((void**)&emb_self, g_emb_self);
    cudaGetSymbolAddress((void**)&S,        g_S);
    cudaGetSymbolAddress((void**)&cat,      g_cat);
    cudaGetSymbolAddress((void**)&hbuf,     g_h);

    const int RPB = 32;
    self_kernel<<<B_SZ / RPB, 256>>>(inputs, W_self, b_self, RPB);

    // Fused: [S_other|S_box|S_ramp] raw -> g_S (768 cols), gi=tanh(.)+b_fc -> cat[:,0:256]
    sgemm128<true><<<dim3(8, B_SZ / 128), 256>>>(
        emb_self, HDIM, HDIM,
        corr_other, corr_box, corr_ramp, W_fc, /*ldb*/0,
        b_fc, S, 768, cat, 1024, /*tanh_col0*/768);

    attn_kernel<N_OTHER, 10, OFF_OTHER, 0,   1 * HDIM><<<B_SZ / 8, 256>>>(inputs, S, W_other, b_other);
    attn_kernel<N_BOX,   13, OFF_BOX,   256, 2 * HDIM><<<B_SZ / 8, 256>>>(inputs, S, W_box, b_box);
    attn_kernel<N_RAMP,  12, OFF_RAMP,  512, 3 * HDIM><<<B_SZ / 8, 256>>>(inputs, S, W_ramp, b_ramp);

    // h = tanh(cat @ W_e1 + b_e1)
    sgemm128<false><<<dim3(2, B_SZ / 128), 256>>>(
        cat, 1024, 1024, W_e1, nullptr, nullptr, nullptr, HDIM,
        b_e1, nullptr, 0, hbuf, HDIM, 0);
    // out = tanh(h @ W_e2 + b_e2)
    sgemm128<false><<<dim3(2, B_SZ / 128), 256>>>(
        hbuf, HDIM, HDIM, W_e2, nullptr, nullptr, nullptr, HDIM,
        b_e2, nullptr, 0, out, HDIM, 0);
}

// round 3
// speedup vs baseline: 1.4868x; 1.0504x over previous
#include <cuda_runtime.h>
#include <math.h>

// Problem constants (fixed: ADV=8, GOOD=8, BOX=16, RAMP=8)
#define B_SZ   32768
#define HDIM   256
#define OBS    464
#define N_OTHER 15
#define N_BOX   16
#define N_RAMP  8
#define OFF_OTHER 10
#define OFF_BOX   160
#define OFF_RAMP  368

// Scratch (static device globals — allocation-free)
__device__ float g_emb_self[B_SZ * HDIM];              // 33.5 MB
__device__ float g_S[(size_t)B_SZ * 768];              // 100 MB  [S_other|S_box|S_ramp]
__device__ float g_cat[(size_t)B_SZ * 1024];           // 134 MB  [gi|vi_other|vi_box|vi_ramp]
__device__ float g_h[B_SZ * HDIM];                     // 33.5 MB

__device__ __forceinline__ float fast_tanh(float x) {
    float y;
    asm("tanh.approx.f32 %0, %1;" : "=f"(y) : "f"(x));
    return y;
}

// ---------------------------------------------------------------------------
// Kernel 1: emb_self = tanh(inputs[:, :10] @ W_self + b_self)
// ---------------------------------------------------------------------------
__global__ void self_kernel(const float* __restrict__ inputs,
                            const float* __restrict__ W,
                            const float* __restrict__ b,
                            int rows_per_block) {
    __shared__ float Ws[10 * HDIM];
    __shared__ float bs[HDIM];
    int tid = threadIdx.x;
    for (int i = tid; i < 10 * HDIM; i += blockDim.x) Ws[i] = W[i];
    if (tid < HDIM) bs[tid] = b[tid];
    __syncthreads();

    int row0 = blockIdx.x * rows_per_block;
    for (int r = 0; r < rows_per_block; ++r) {
        int row = row0 + r;
        const float* in = inputs + (size_t)row * OBS;
        float acc = bs[tid];
#pragma unroll
        for (int f = 0; f < 10; ++f) acc += in[f] * Ws[f * HDIM + tid];
        g_emb_self[(size_t)row * HDIM + tid] = fast_tanh(acc);
    }
}

// ---------------------------------------------------------------------------
// SGEMM 128x128x8, 256 threads, 8x8 microtile, double-buffered smem.
// FUSED=true:  B = [B0|B1|B2|B3] (each 256x256), N=1024.
//              cols [0,768) raw -> Cs; cols [768,1024) tanh(+bias) -> Ct.
// FUSED=false: single B0, all cols tanh(+bias) -> Ct.
// ---------------------------------------------------------------------------
template <bool FUSED>
__global__ __launch_bounds__(256)
void sgemm128(const float* __restrict__ A, int lda, int K,
              const float* __restrict__ B0, const float* __restrict__ B1,
              const float* __restrict__ B2, const float* __restrict__ B3,
              int ldb,
              const float* __restrict__ bias,
              float* __restrict__ Cs, int ldcs,
              float* __restrict__ Ct, int ldct, int tanh_col0) {
    __shared__ float As[2][8][128];
    __shared__ float Bs[2][8][128];

    int tid = threadIdx.x;
    int m0 = blockIdx.y * 128;
    int n0 = blockIdx.x * 128;

    const float* Bp;
    if (FUSED) {
        const float* sel = (n0 < 256) ? B0 : (n0 < 512) ? B1 : (n0 < 768) ? B2 : B3;
        Bp = sel + (n0 & 255);
        ldb = 256;
    } else {
        Bp = B0 + n0;
    }
    const float* Ap = A + (size_t)m0 * lda;

    int arow = tid >> 1;
    int acol = (tid & 1) * 4;
    int bk   = tid >> 5;
    int bn   = (tid & 31) * 4;
    int tr = (tid >> 4) * 4;
    int tc = (tid & 15) * 4;

    float4 aR = *(const float4*)(Ap + (size_t)arow * lda + acol);
    float4 bR = *(const float4*)(Bp + (size_t)bk * ldb + bn);
    As[0][acol + 0][arow] = aR.x; As[0][acol + 1][arow] = aR.y;
    As[0][acol + 2][arow] = aR.z; As[0][acol + 3][arow] = aR.w;
    *(float4*)&Bs[0][bk][bn] = bR;
    __syncthreads();

    float acc[8][8] = {};
    int nt = K >> 3;
    for (int t = 0; t < nt; ++t) {
        int cur = t & 1;
        if (t + 1 < nt) {
            aR = *(const float4*)(Ap + (size_t)arow * lda + (t + 1) * 8 + acol);
            bR = *(const float4*)(Bp + (size_t)((t + 1) * 8 + bk) * ldb + bn);
        }
#pragma unroll
        for (int kk = 0; kk < 8; ++kk) {
            float4 a0 = *(const float4*)&As[cur][kk][tr];
            float4 a1 = *(const float4*)&As[cur][kk][tr + 64];
            float4 b0 = *(const float4*)&Bs[cur][kk][tc];
            float4 b1 = *(const float4*)&Bs[cur][kk][tc + 64];
            float av[8] = {a0.x, a0.y, a0.z, a0.w, a1.x, a1.y, a1.z, a1.w};
            float bv[8] = {b0.x, b0.y, b0.z, b0.w, b1.x, b1.y, b1.z, b1.w};
#pragma unroll
            for (int i = 0; i < 8; ++i)
#pragma unroll
                for (int j = 0; j < 8; ++j)
                    acc[i][j] += av[i] * bv[j];
        }
        if (t + 1 < nt) {
            int nx = cur ^ 1;
            As[nx][acol + 0][arow] = aR.x; As[nx][acol + 1][arow] = aR.y;
            As[nx][acol + 2][arow] = aR.z; As[nx][acol + 3][arow] = aR.w;
            *(float4*)&Bs[nx][bk][bn] = bR;
        }
        __syncthreads();
    }

    bool do_tanh = (n0 >= tanh_col0);
#pragma unroll
    for (int i = 0; i < 8; ++i) {
        int row = m0 + ((i < 4) ? (tr + i) : (tr + 64 + i - 4));
        if (do_tanh) {
            int cbase = n0 - tanh_col0;
            float* outp = Ct + (size_t)row * ldct + cbase;
            float4 v0, v1;
            v0.x = fast_tanh(acc[i][0] + bias[cbase + tc + 0]);
            v0.y = fast_tanh(acc[i][1] + bias[cbase + tc + 1]);
            v0.z = fast_tanh(acc[i][2] + bias[cbase + tc + 2]);
            v0.w = fast_tanh(acc[i][3] + bias[cbase + tc + 3]);
            v1.x = fast_tanh(acc[i][4] + bias[cbase + tc + 64]);
            v1.y = fast_tanh(acc[i][5] + bias[cbase + tc + 65]);
            v1.z = fast_tanh(acc[i][6] + bias[cbase + tc + 66]);
            v1.w = fast_tanh(acc[i][7] + bias[cbase + tc + 67]);
            *(float4*)(outp + tc) = v0;
            *(float4*)(outp + tc + 64) = v1;
        } else {
            float* outp = Cs + (size_t)row * ldcs + n0;
            *(float4*)(outp + tc)      = make_float4(acc[i][0], acc[i][1], acc[i][2], acc[i][3]);
            *(float4*)(outp + tc + 64) = make_float4(acc[i][4], acc[i][5], acc[i][6], acc[i][7]);
        }
    }
}

// ---------------------------------------------------------------------------
// Attention pool, register-resident W: each lane caches W[f][j*32+lane] for
// its 8 h-values (<=104 regs). Persistent warps grid-stride over rows.
// Inner loop is pure FFMA + MUFU (no shared memory at all).
// ---------------------------------------------------------------------------
template <int NENT, int FDIM, int IN_OFF, int GOFF, int CAT_OFF>
__global__ __launch_bounds__(256)
void attn_kernel(const float* __restrict__ inputs,
                 const float* __restrict__ S,
                 const float* __restrict__ W,
                 const float* __restrict__ b) {
    int tid = threadIdx.x;
    int warp = tid >> 5, lane = tid & 31;

    // Register-cached weights & bias for this lane's 8 h-positions.
    float wreg[8][FDIM];
    float breg[8];
#pragma unroll
    for (int j = 0; j < 8; ++j) {
        int h = j * 32 + lane;
        breg[j] = __ldg(b + h);
#pragma unroll
        for (int f = 0; f < FDIM; ++f)
            wreg[j][f] = __ldg(W + f * HDIM + h);
    }

    int step = gridDim.x * 8;
    for (int row = blockIdx.x * 8 + warp; row < B_SZ; row += step) {
        float s[8], acc[8];
#pragma unroll
        for (int j = 0; j < 8; ++j) {
            s[j] = S[(size_t)row * 768 + GOFF + j * 32 + lane];
            acc[j] = 0.f;
        }
        float m = -INFINITY, l = 0.f;
        const float* rowin = inputs + (size_t)row * OBS + IN_OFF;

#pragma unroll 1
        for (int n = 0; n < NENT; ++n) {
            const float* ent = rowin + n * FDIM;
            float feat[FDIM];
#pragma unroll
            for (int f = 0; f < FDIM; ++f) feat[f] = __ldg(ent + f);  // uniform

            float e[8];
#pragma unroll
            for (int j = 0; j < 8; ++j) {
                float a = breg[j];
#pragma unroll
                for (int f = 0; f < FDIM; ++f) a += feat[f] * wreg[j][f];
                e[j] = fast_tanh(a);
            }

            float bp = 0.f;
#pragma unroll
            for (int j = 0; j < 8; ++j) bp += s[j] * e[j];
#pragma unroll
            for (int off = 16; off > 0; off >>= 1)
                bp += __shfl_xor_sync(0xFFFFFFFFu, bp, off);

            float mn = fmaxf(m, bp);
            float cr = __expf(m - mn);   // first iter: exp(-inf)=0
            float w  = __expf(bp - mn);
#pragma unroll
            for (int j = 0; j < 8; ++j) acc[j] = acc[j] * cr + w * e[j];
            l = l * cr + w;
            m = mn;
        }

        float inv = 1.f / l;
#pragma unroll
        for (int j = 0; j < 8; ++j)
            g_cat[(size_t)row * 1024 + CAT_OFF + j * 32 + lane] = acc[j] * inv;
    }
}

// ---------------------------------------------------------------------------
extern "C" void kernel_launch(void* const* d_in, const int* in_sizes, int n_in,
                              void* d_out, int out_size) {
    const float* inputs     = (const float*)d_in[0];
    const float* W_self     = (const float*)d_in[1];
    const float* b_self     = (const float*)d_in[2];
    const float* W_other    = (const float*)d_in[3];
    const float* b_other    = (const float*)d_in[4];
    const float* W_box      = (const float*)d_in[5];
    const float* b_box      = (const float*)d_in[6];
    const float* W_ramp     = (const float*)d_in[7];
    const float* b_ramp     = (const float*)d_in[8];
    const float* corr_other = (const float*)d_in[9];
    const float* corr_box   = (const float*)d_in[10];
    const float* corr_ramp  = (const float*)d_in[11];
    const float* W_fc       = (const float*)d_in[12];
    const float* b_fc       = (const float*)d_in[13];
    const float* W_e1       = (const float*)d_in[14];
    const float* b_e1       = (const float*)d_in[15];
    const float* W_e2       = (const float*)d_in[16];
    const float* b_e2       = (const float*)d_in[17];
    float* out = (float*)d_out;

    float *emb_self, *S, *cat, *hbuf;
    cudaGetSymbolAddress((void**)&emb_self, g_emb_self);
    cudaGetSymbolAddress((void**)&S,        g_S);
    cudaGetSymbolAddress((void**)&cat,      g_cat);
    cudaGetSymbolAddress((void**)&hbuf,     g_h);

    const int RPB = 32;
    self_kernel<<<B_SZ / RPB, 256>>>(inputs, W_self, b_self, RPB);

    // Fused: [S_other|S_box|S_ramp] raw -> g_S (768 cols), gi=tanh(.)+b_fc -> cat[:,0:256]
    sgemm128<true><<<dim3(8, B_SZ / 128), 256>>>(
        emb_self, HDIM, HDIM,
        corr_other, corr_box, corr_ramp, W_fc, /*ldb*/0,
        b_fc, S, 768, cat, 1024, /*tanh_col0*/768);

    const int ATTN_BLOCKS = 1024;  // persistent-ish: 4 rows per warp
    attn_kernel<N_OTHER, 10, OFF_OTHER, 0,   1 * HDIM><<<ATTN_BLOCKS, 256>>>(inputs, S, W_other, b_other);
    attn_kernel<N_BOX,   13, OFF_BOX,   256, 2 * HDIM><<<ATTN_BLOCKS, 256>>>(inputs, S, W_box, b_box);
    attn_kernel<N_RAMP,  12, OFF_RAMP,  512, 3 * HDIM><<<ATTN_BLOCKS, 256>>>(inputs, S, W_ramp, b_ramp);

    // h = tanh(cat @ W_e1 + b_e1)
    sgemm128<false><<<dim3(2, B_SZ / 128), 256>>>(
        cat, 1024, 1024, W_e1, nullptr, nullptr, nullptr, HDIM,
        b_e1, nullptr, 0, hbuf, HDIM, 0);
    // out = tanh(h @ W_e2 + b_e2)
    sgemm128<false><<<dim3(2, B_SZ / 128), 256>>>(
        hbuf, HDIM, HDIM, W_e2, nullptr, nullptr, nullptr, HDIM,
        b_e2, nullptr, 0, out, HDIM, 0);
}

// round 4
// speedup vs baseline: 1.5383x; 1.0346x over previous
#include <cuda_runtime.h>
#include <math.h>

// Problem constants (fixed: ADV=8, GOOD=8, BOX=16, RAMP=8)
#define B_SZ   32768
#define HDIM   256
#define OBS    464
#define N_OTHER 15
#define N_BOX   16
#define N_RAMP  8
#define OFF_OTHER 10
#define OFF_BOX   160
#define OFF_RAMP  368

// Scratch (static device globals — allocation-free)
__device__ float g_emb_self[B_SZ * HDIM];              // 33.5 MB
__device__ float g_S[(size_t)B_SZ * 768];              // 100 MB  [S_other|S_box|S_ramp]
__device__ float g_cat[(size_t)B_SZ * 1024];           // 134 MB  [gi|vi_other|vi_box|vi_ramp]
__device__ float g_h[B_SZ * HDIM];                     // 33.5 MB

__device__ __forceinline__ float fast_tanh(float x) {
    float y;
    asm("tanh.approx.f32 %0, %1;" : "=f"(y) : "f"(x));
    return y;
}

// ---------------------------------------------------------------------------
// Kernel 1: emb_self = tanh(inputs[:, :10] @ W_self + b_self)
// ---------------------------------------------------------------------------
__global__ void self_kernel(const float* __restrict__ inputs,
                            const float* __restrict__ W,
                            const float* __restrict__ b,
                            int rows_per_block) {
    __shared__ float Ws[10 * HDIM];
    __shared__ float bs[HDIM];
    int tid = threadIdx.x;
    for (int i = tid; i < 10 * HDIM; i += blockDim.x) Ws[i] = W[i];
    if (tid < HDIM) bs[tid] = b[tid];
    __syncthreads();

    int row0 = blockIdx.x * rows_per_block;
    for (int r = 0; r < rows_per_block; ++r) {
        int row = row0 + r;
        const float* in = inputs + (size_t)row * OBS;
        float acc = bs[tid];
#pragma unroll
        for (int f = 0; f < 10; ++f) acc += in[f] * Ws[f * HDIM + tid];
        g_emb_self[(size_t)row * HDIM + tid] = fast_tanh(acc);
    }
}

// ---------------------------------------------------------------------------
// SGEMM 128x128x8, 256 threads, 8x8 microtile, double-buffered smem.
// FUSED=true:  B = [B0|B1|B2|B3] (each 256x256), N=1024.
//              cols [0,768) raw -> Cs; cols [768,1024) tanh(+bias) -> Ct.
// FUSED=false: single B0, all cols tanh(+bias) -> Ct.
// ---------------------------------------------------------------------------
template <bool FUSED>
__global__ __launch_bounds__(256)
void sgemm128(const float* __restrict__ A, int lda, int K,
              const float* __restrict__ B0, const float* __restrict__ B1,
              const float* __restrict__ B2, const float* __restrict__ B3,
              int ldb,
              const float* __restrict__ bias,
              float* __restrict__ Cs, int ldcs,
              float* __restrict__ Ct, int ldct, int tanh_col0) {
    __shared__ float As[2][8][128];
    __shared__ float Bs[2][8][128];

    int tid = threadIdx.x;
    int m0 = blockIdx.y * 128;
    int n0 = blockIdx.x * 128;

    const float* Bp;
    if (FUSED) {
        const float* sel = (n0 < 256) ? B0 : (n0 < 512) ? B1 : (n0 < 768) ? B2 : B3;
        Bp = sel + (n0 & 255);
        ldb = 256;
    } else {
        Bp = B0 + n0;
    }
    const float* Ap = A + (size_t)m0 * lda;

    int arow = tid >> 1;
    int acol = (tid & 1) * 4;
    int bk   = tid >> 5;
    int bn   = (tid & 31) * 4;
    int tr = (tid >> 4) * 4;
    int tc = (tid & 15) * 4;

    float4 aR = *(const float4*)(Ap + (size_t)arow * lda + acol);
    float4 bR = *(const float4*)(Bp + (size_t)bk * ldb + bn);
    As[0][acol + 0][arow] = aR.x; As[0][acol + 1][arow] = aR.y;
    As[0][acol + 2][arow] = aR.z; As[0][acol + 3][arow] = aR.w;
    *(float4*)&Bs[0][bk][bn] = bR;
    __syncthreads();

    float acc[8][8] = {};
    int nt = K >> 3;
    for (int t = 0; t < nt; ++t) {
        int cur = t & 1;
        if (t + 1 < nt) {
            aR = *(const float4*)(Ap + (size_t)arow * lda + (t + 1) * 8 + acol);
            bR = *(const float4*)(Bp + (size_t)((t + 1) * 8 + bk) * ldb + bn);
        }
#pragma unroll
        for (int kk = 0; kk < 8; ++kk) {
            float4 a0 = *(const float4*)&As[cur][kk][tr];
            float4 a1 = *(const float4*)&As[cur][kk][tr + 64];
            float4 b0 = *(const float4*)&Bs[cur][kk][tc];
            float4 b1 = *(const float4*)&Bs[cur][kk][tc + 64];
            float av[8] = {a0.x, a0.y, a0.z, a0.w, a1.x, a1.y, a1.z, a1.w};
            float bv[8] = {b0.x, b0.y, b0.z, b0.w, b1.x, b1.y, b1.z, b1.w};
#pragma unroll
            for (int i = 0; i < 8; ++i)
#pragma unroll
                for (int j = 0; j < 8; ++j)
                    acc[i][j] += av[i] * bv[j];
        }
        if (t + 1 < nt) {
            int nx = cur ^ 1;
            As[nx][acol + 0][arow] = aR.x; As[nx][acol + 1][arow] = aR.y;
            As[nx][acol + 2][arow] = aR.z; As[nx][acol + 3][arow] = aR.w;
            *(float4*)&Bs[nx][bk][bn] = bR;
        }
        __syncthreads();
    }

    bool do_tanh = (n0 >= tanh_col0);
#pragma unroll
    for (int i = 0; i < 8; ++i) {
        int row = m0 + ((i < 4) ? (tr + i) : (tr + 64 + i - 4));
        if (do_tanh) {
            int cbase = n0 - tanh_col0;
            float* outp = Ct + (size_t)row * ldct + cbase;
            float4 v0, v1;
            v0.x = fast_tanh(acc[i][0] + bias[cbase + tc + 0]);
            v0.y = fast_tanh(acc[i][1] + bias[cbase + tc + 1]);
            v0.z = fast_tanh(acc[i][2] + bias[cbase + tc + 2]);
            v0.w = fast_tanh(acc[i][3] + bias[cbase + tc + 3]);
            v1.x = fast_tanh(acc[i][4] + bias[cbase + tc + 64]);
            v1.y = fast_tanh(acc[i][5] + bias[cbase + tc + 65]);
            v1.z = fast_tanh(acc[i][6] + bias[cbase + tc + 66]);
            v1.w = fast_tanh(acc[i][7] + bias[cbase + tc + 67]);
            *(float4*)(outp + tc) = v0;
            *(float4*)(outp + tc + 64) = v1;
        } else {
            float* outp = Cs + (size_t)row * ldcs + n0;
            *(float4*)(outp + tc)      = make_float4(acc[i][0], acc[i][1], acc[i][2], acc[i][3]);
            *(float4*)(outp + tc + 64) = make_float4(acc[i][4], acc[i][5], acc[i][6], acc[i][7]);
        }
    }
}

// ---------------------------------------------------------------------------
// Attention pool, register-resident W, NO online softmax (exp taken directly;
// |beta| <~ 50 here so fp32 exp is safe and results are mathematically
// identical to max-subtracted softmax). This removes the serial rescale chain
// so entity n+1's FFMA block overlaps entity n's shuffle/exp tail.
// ---------------------------------------------------------------------------
template <int NENT, int FDIM, int IN_OFF, int GOFF, int CAT_OFF>
__global__ __launch_bounds__(256)
void attn_kernel(const float* __restrict__ inputs,
                 const float* __restrict__ S,
                 const float* __restrict__ W,
                 const float* __restrict__ b) {
    int tid = threadIdx.x;
    int warp = tid >> 5, lane = tid & 31;

    // Register-cached weights & bias for this lane's 8 h-positions.
    float wreg[8][FDIM];
    float breg[8];
#pragma unroll
    for (int j = 0; j < 8; ++j) {
        int h = j * 32 + lane;
        breg[j] = __ldg(b + h);
#pragma unroll
        for (int f = 0; f < FDIM; ++f)
            wreg[j][f] = __ldg(W + f * HDIM + h);
    }

    int step = gridDim.x * 8;
    for (int row = blockIdx.x * 8 + warp; row < B_SZ; row += step) {
        float s[8], acc[8];
#pragma unroll
        for (int j = 0; j < 8; ++j) {
            s[j] = S[(size_t)row * 768 + GOFF + j * 32 + lane];
            acc[j] = 0.f;
        }
        float l = 0.f;
        const float* rowin = inputs + (size_t)row * OBS + IN_OFF;

#pragma unroll 2
        for (int n = 0; n < NENT; ++n) {
            const float* ent = rowin + n * FDIM;
            float feat[FDIM];
#pragma unroll
            for (int f = 0; f < FDIM; ++f) feat[f] = __ldg(ent + f);  // uniform

            float e[8];
#pragma unroll
            for (int j = 0; j < 8; ++j) {
                float a = breg[j];
#pragma unroll
                for (int f = 0; f < FDIM; ++f) a += feat[f] * wreg[j][f];
                e[j] = fast_tanh(a);
            }

            float bp = 0.f;
#pragma unroll
            for (int j = 0; j < 8; ++j) bp += s[j] * e[j];
#pragma unroll
            for (int off = 16; off > 0; off >>= 1)
                bp += __shfl_xor_sync(0xFFFFFFFFu, bp, off);

            float w = __expf(bp);
            l += w;
#pragma unroll
            for (int j = 0; j < 8; ++j) acc[j] += w * e[j];
        }

        float inv = 1.f / l;
#pragma unroll
        for (int j = 0; j < 8; ++j)
            g_cat[(size_t)row * 1024 + CAT_OFF + j * 32 + lane] = acc[j] * inv;
    }
}

// ---------------------------------------------------------------------------
extern "C" void kernel_launch(void* const* d_in, const int* in_sizes, int n_in,
                              void* d_out, int out_size) {
    const float* inputs     = (const float*)d_in[0];
    const float* W_self     = (const float*)d_in[1];
    const float* b_self     = (const float*)d_in[2];
    const float* W_other    = (const float*)d_in[3];
    const float* b_other    = (const float*)d_in[4];
    const float* W_box      = (const float*)d_in[5];
    const float* b_box      = (const float*)d_in[6];
    const float* W_ramp     = (const float*)d_in[7];
    const float* b_ramp     = (const float*)d_in[8];
    const float* corr_other = (const float*)d_in[9];
    const float* corr_box   = (const float*)d_in[10];
    const float* corr_ramp  = (const float*)d_in[11];
    const float* W_fc       = (const float*)d_in[12];
    const float* b_fc       = (const float*)d_in[13];
    const float* W_e1       = (const float*)d_in[14];
    const float* b_e1       = (const float*)d_in[15];
    const float* W_e2       = (const float*)d_in[16];
    const float* b_e2       = (const float*)d_in[17];
    float* out = (float*)d_out;

    float *emb_self, *S, *cat, *hbuf;
    cudaGetSymbolAddress((void**)&emb_self, g_emb_self);
    cudaGetSymbolAddress((void**)&S,        g_S);
    cudaGetSymbolAddress((void**)&cat,      g_cat);
    cudaGetSymbolAddress((void**)&hbuf,     g_h);

    const int RPB = 32;
    self_kernel<<<B_SZ / RPB, 256>>>(inputs, W_self, b_self, RPB);

    // Fused: [S_other|S_box|S_ramp] raw -> g_S (768 cols), gi=tanh(.)+b_fc -> cat[:,0:256]
    sgemm128<true><<<dim3(8, B_SZ / 128), 256>>>(
        emb_self, HDIM, HDIM,
        corr_other, corr_box, corr_ramp, W_fc, /*ldb*/0,
        b_fc, S, 768, cat, 1024, /*tanh_col0*/768);

    const int ATTN_BLOCKS = 1024;  // 4 rows per warp
    attn_kernel<N_OTHER, 10, OFF_OTHER, 0,   1 * HDIM><<<ATTN_BLOCKS, 256>>>(inputs, S, W_other, b_other);
    attn_kernel<N_BOX,   13, OFF_BOX,   256, 2 * HDIM><<<ATTN_BLOCKS, 256>>>(inputs, S, W_box, b_box);
    attn_kernel<N_RAMP,  12, OFF_RAMP,  512, 3 * HDIM><<<ATTN_BLOCKS, 256>>>(inputs, S, W_ramp, b_ramp);

    // h = tanh(cat @ W_e1 + b_e1)
    sgemm128<false><<<dim3(2, B_SZ / 128), 256>>>(
        cat, 1024, 1024, W_e1, nullptr, nullptr, nullptr, HDIM,
        b_e1, nullptr, 0, hbuf, HDIM, 0);
    // out = tanh(h @ W_e2 + b_e2)
    sgemm128<false><<<dim3(2, B_SZ / 128), 256>>>(
        hbuf, HDIM, HDIM, W_e2, nullptr, nullptr, nullptr, HDIM,
        b_e2, nullptr, 0, out, HDIM, 0);
}

// round 5
// speedup vs baseline: 1.5921x; 1.0350x over previous
#include <cuda_runtime.h>
#include <math.h>

// Problem constants (fixed: ADV=8, GOOD=8, BOX=16, RAMP=8)
#define B_SZ   32768
#define HDIM   256
#define OBS    464
#define N_OTHER 15
#define N_BOX   16
#define N_RAMP  8
#define OFF_OTHER 10
#define OFF_BOX   160
#define OFF_RAMP  368

// Scratch (static device globals — allocation-free)
__device__ float g_emb_self[B_SZ * HDIM];              // 33.5 MB
__device__ float g_S[(size_t)B_SZ * 768];              // 100 MB  [S_other|S_box|S_ramp]
__device__ float g_cat[(size_t)B_SZ * 1024];           // 134 MB  [gi|vi_other|vi_box|vi_ramp]
__device__ float g_h[B_SZ * HDIM];                     // 33.5 MB

__device__ __forceinline__ float fast_tanh(float x) {
    float y;
    asm("tanh.approx.f32 %0, %1;" : "=f"(y) : "f"(x));
    return y;
}

// ---------------------------------------------------------------------------
// Kernel 1: emb_self = tanh(inputs[:, :10] @ W_self + b_self)
// ---------------------------------------------------------------------------
__global__ void self_kernel(const float* __restrict__ inputs,
                            const float* __restrict__ W,
                            const float* __restrict__ b,
                            int rows_per_block) {
    __shared__ float Ws[10 * HDIM];
    __shared__ float bs[HDIM];
    int tid = threadIdx.x;
    for (int i = tid; i < 10 * HDIM; i += blockDim.x) Ws[i] = W[i];
    if (tid < HDIM) bs[tid] = b[tid];
    __syncthreads();

    int row0 = blockIdx.x * rows_per_block;
    for (int r = 0; r < rows_per_block; ++r) {
        int row = row0 + r;
        const float* in = inputs + (size_t)row * OBS;
        float acc = bs[tid];
#pragma unroll
        for (int f = 0; f < 10; ++f) acc += in[f] * Ws[f * HDIM + tid];
        g_emb_self[(size_t)row * HDIM + tid] = fast_tanh(acc);
    }
}

// ---------------------------------------------------------------------------
// SGEMM 128x128x8, 256 threads, 8x8 microtile, double-buffered smem.
// FUSED=true:  B = [B0|B1|B2|B3] (each 256x256), N=1024.
//              cols [0,768) raw -> Cs; cols [768,1024) tanh(+bias) -> Ct.
// FUSED=false: single B0, all cols tanh(+bias) -> Ct.
// ---------------------------------------------------------------------------
template <bool FUSED>
__global__ __launch_bounds__(256)
void sgemm128(const float* __restrict__ A, int lda, int K,
              const float* __restrict__ B0, const float* __restrict__ B1,
              const float* __restrict__ B2, const float* __restrict__ B3,
              int ldb,
              const float* __restrict__ bias,
              float* __restrict__ Cs, int ldcs,
              float* __restrict__ Ct, int ldct, int tanh_col0) {
    __shared__ float As[2][8][128];
    __shared__ float Bs[2][8][128];

    int tid = threadIdx.x;
    int m0 = blockIdx.y * 128;
    int n0 = blockIdx.x * 128;

    const float* Bp;
    if (FUSED) {
        const float* sel = (n0 < 256) ? B0 : (n0 < 512) ? B1 : (n0 < 768) ? B2 : B3;
        Bp = sel + (n0 & 255);
        ldb = 256;
    } else {
        Bp = B0 + n0;
    }
    const float* Ap = A + (size_t)m0 * lda;

    int arow = tid >> 1;
    int acol = (tid & 1) * 4;
    int bk   = tid >> 5;
    int bn   = (tid & 31) * 4;
    int tr = (tid >> 4) * 4;
    int tc = (tid & 15) * 4;

    float4 aR = *(const float4*)(Ap + (size_t)arow * lda + acol);
    float4 bR = *(const float4*)(Bp + (size_t)bk * ldb + bn);
    As[0][acol + 0][arow] = aR.x; As[0][acol + 1][arow] = aR.y;
    As[0][acol + 2][arow] = aR.z; As[0][acol + 3][arow] = aR.w;
    *(float4*)&Bs[0][bk][bn] = bR;
    __syncthreads();

    float acc[8][8] = {};
    int nt = K >> 3;
    for (int t = 0; t < nt; ++t) {
        int cur = t & 1;
        if (t + 1 < nt) {
            aR = *(const float4*)(Ap + (size_t)arow * lda + (t + 1) * 8 + acol);
            bR = *(const float4*)(Bp + (size_t)((t + 1) * 8 + bk) * ldb + bn);
        }
#pragma unroll
        for (int kk = 0; kk < 8; ++kk) {
            float4 a0 = *(const float4*)&As[cur][kk][tr];
            float4 a1 = *(const float4*)&As[cur][kk][tr + 64];
            float4 b0 = *(const float4*)&Bs[cur][kk][tc];
            float4 b1 = *(const float4*)&Bs[cur][kk][tc + 64];
            float av[8] = {a0.x, a0.y, a0.z, a0.w, a1.x, a1.y, a1.z, a1.w};
            float bv[8] = {b0.x, b0.y, b0.z, b0.w, b1.x, b1.y, b1.z, b1.w};
#pragma unroll
            for (int i = 0; i < 8; ++i)
#pragma unroll
                for (int j = 0; j < 8; ++j)
                    acc[i][j] += av[i] * bv[j];
        }
        if (t + 1 < nt) {
            int nx = cur ^ 1;
            As[nx][acol + 0][arow] = aR.x; As[nx][acol + 1][arow] = aR.y;
            As[nx][acol + 2][arow] = aR.z; As[nx][acol + 3][arow] = aR.w;
            *(float4*)&Bs[nx][bk][bn] = bR;
        }
        __syncthreads();
    }

    bool do_tanh = (n0 >= tanh_col0);
#pragma unroll
    for (int i = 0; i < 8; ++i) {
        int row = m0 + ((i < 4) ? (tr + i) : (tr + 64 + i - 4));
        if (do_tanh) {
            int cbase = n0 - tanh_col0;
            float* outp = Ct + (size_t)row * ldct + cbase;
            float4 v0, v1;
            v0.x = fast_tanh(acc[i][0] + bias[cbase + tc + 0]);
            v0.y = fast_tanh(acc[i][1] + bias[cbase + tc + 1]);
            v0.z = fast_tanh(acc[i][2] + bias[cbase + tc + 2]);
            v0.w = fast_tanh(acc[i][3] + bias[cbase + tc + 3]);
            v1.x = fast_tanh(acc[i][4] + bias[cbase + tc + 64]);
            v1.y = fast_tanh(acc[i][5] + bias[cbase + tc + 65]);
            v1.z = fast_tanh(acc[i][6] + bias[cbase + tc + 66]);
            v1.w = fast_tanh(acc[i][7] + bias[cbase + tc + 67]);
            *(float4*)(outp + tc) = v0;
            *(float4*)(outp + tc + 64) = v1;
        } else {
            float* outp = Cs + (size_t)row * ldcs + n0;
            *(float4*)(outp + tc)      = make_float4(acc[i][0], acc[i][1], acc[i][2], acc[i][3]);
            *(float4*)(outp + tc + 64) = make_float4(acc[i][4], acc[i][5], acc[i][6], acc[i][7]);
        }
    }
}

// ---------------------------------------------------------------------------
// Attention pool v3: warp-PAIR per row.
//  - Each warp owns 128 of the 256 h-dims (4 chunks of 32) -> wreg 52 regs,
//    ~95 regs total -> 2 blocks/SM (25% occupancy).
//  - Entity features staged through smem (coalesced LDG once per row; LDS
//    broadcast in the entity loop) instead of uniform LDGs per entity.
//  - beta combined across the warp pair via parity-double-buffered smem
//    slot + one __syncthreads per entity.
// Block: 256 threads = 8 warps = 4 rows. No online softmax (|beta| small).
// ---------------------------------------------------------------------------
template <int NENT, int FDIM, int IN_OFF, int GOFF, int CAT_OFF>
__global__ __launch_bounds__(256, 2)
void attn_kernel(const float* __restrict__ inputs,
                 const float* __restrict__ S,
                 const float* __restrict__ W,
                 const float* __restrict__ b) {
    constexpr int FT = NENT * FDIM;
    constexpr int FHALF = FT / 2;
    __shared__ float sfeat[4][FT];
    __shared__ float sred[2][2][4];   // [entity parity][warp half][row slot]

    int tid = threadIdx.x;
    int warp = tid >> 5, lane = tid & 31;
    int slot = warp >> 1;   // row slot 0..3
    int half = warp & 1;    // which 128 h-dims this warp owns

    // Register-cached weights/bias for this warp's 4 h-chunks.
    float wreg[4][FDIM], breg[4];
#pragma unroll
    for (int j = 0; j < 4; ++j) {
        int h = j * 64 + half * 32 + lane;
        breg[j] = __ldg(b + h);
#pragma unroll
        for (int f = 0; f < FDIM; ++f)
            wreg[j][f] = __ldg(W + f * HDIM + h);
    }

    int step = gridDim.x * 4;
    for (int row0 = blockIdx.x * 4; row0 < B_SZ; row0 += step) {
        int row = row0 + slot;

        // Stage this row's entity features: warp loads its half, coalesced.
        {
            const float* rowin = inputs + (size_t)row * OBS + IN_OFF;
            int lo = half * FHALF;
            int hi = half ? FT : FHALF;
            for (int i = lo + lane; i < hi; i += 32)
                sfeat[slot][i] = rowin[i];
        }
        __syncthreads();   // features visible; also fences prior sred reads

        float s[4], acc[4];
#pragma unroll
        for (int j = 0; j < 4; ++j) {
            s[j] = S[(size_t)row * 768 + GOFF + j * 64 + half * 32 + lane];
            acc[j] = 0.f;
        }
        float l = 0.f;

#pragma unroll 1
        for (int n = 0; n < NENT; ++n) {
            const float* feat = &sfeat[slot][n * FDIM];

            float e[4];
#pragma unroll
            for (int j = 0; j < 4; ++j) {
                float a = breg[j];
#pragma unroll
                for (int f = 0; f < FDIM; ++f) a += feat[f] * wreg[j][f];
                e[j] = fast_tanh(a);
            }

            float p = 0.f;
#pragma unroll
            for (int j = 0; j < 4; ++j) p += s[j] * e[j];
#pragma unroll
            for (int off = 16; off > 0; off >>= 1)
                p += __shfl_xor_sync(0xFFFFFFFFu, p, off);

            if (lane == 0) sred[n & 1][half][slot] = p;
            __syncthreads();
            float bp = sred[n & 1][0][slot] + sred[n & 1][1][slot];

            float w = __expf(bp);
            l += w;
#pragma unroll
            for (int j = 0; j < 4; ++j) acc[j] += w * e[j];
        }

        float inv = 1.f / l;
#pragma unroll
        for (int j = 0; j < 4; ++j)
            g_cat[(size_t)row * 1024 + CAT_OFF + j * 64 + half * 32 + lane] = acc[j] * inv;
    }
}

// ---------------------------------------------------------------------------
extern "C" void kernel_launch(void* const* d_in, const int* in_sizes, int n_in,
                              void* d_out, int out_size) {
    const float* inputs     = (const float*)d_in[0];
    const float* W_self     = (const float*)d_in[1];
    const float* b_self     = (const float*)d_in[2];
    const float* W_other    = (const float*)d_in[3];
    const float* b_other    = (const float*)d_in[4];
    const float* W_box      = (const float*)d_in[5];
    const float* b_box      = (const float*)d_in[6];
    const float* W_ramp     = (const float*)d_in[7];
    const float* b_ramp     = (const float*)d_in[8];
    const float* corr_other = (const float*)d_in[9];
    const float* corr_box   = (const float*)d_in[10];
    const float* corr_ramp  = (const float*)d_in[11];
    const float* W_fc       = (const float*)d_in[12];
    const float* b_fc       = (const float*)d_in[13];
    const float* W_e1       = (const float*)d_in[14];
    const float* b_e1       = (const float*)d_in[15];
    const float* W_e2       = (const float*)d_in[16];
    const float* b_e2       = (const float*)d_in[17];
    float* out = (float*)d_out;

    float *emb_self, *S, *cat, *hbuf;
    cudaGetSymbolAddress((void**)&emb_self, g_emb_self);
    cudaGetSymbolAddress((void**)&S,        g_S);
    cudaGetSymbolAddress((void**)&cat,      g_cat);
    cudaGetSymbolAddress((void**)&hbuf,     g_h);

    const int RPB = 32;
    self_kernel<<<B_SZ / RPB, 256>>>(inputs, W_self, b_self, RPB);

    // Fused: [S_other|S_box|S_ramp] raw -> g_S (768 cols), gi=tanh(.)+b_fc -> cat[:,0:256]
    sgemm128<true><<<dim3(8, B_SZ / 128), 256>>>(
        emb_self, HDIM, HDIM,
        corr_other, corr_box, corr_ramp, W_fc, /*ldb*/0,
        b_fc, S, 768, cat, 1024, /*tanh_col0*/768);

    const int ATTN_BLOCKS = 2048;  // 4 rows/block, 4 grid-stride iters
    attn_kernel<N_OTHER, 10, OFF_OTHER, 0,   1 * HDIM><<<ATTN_BLOCKS, 256>>>(inputs, S, W_other, b_other);
    attn_kernel<N_BOX,   13, OFF_BOX,   256, 2 * HDIM><<<ATTN_BLOCKS, 256>>>(inputs, S, W_box, b_box);
    attn_kernel<N_RAMP,  12, OFF_RAMP,  512, 3 * HDIM><<<ATTN_BLOCKS, 256>>>(inputs, S, W_ramp, b_ramp);

    // h = tanh(cat @ W_e1 + b_e1)
    sgemm128<false><<<dim3(2, B_SZ / 128), 256>>>(
        cat, 1024, 1024, W_e1, nullptr, nullptr, nullptr, HDIM,
        b_e1, nullptr, 0, hbuf, HDIM, 0);
    // out = tanh(h @ W_e2 + b_e2)
    sgemm128<false><<<dim3(2, B_SZ / 128), 256>>>(
        hbuf, HDIM, HDIM, W_e2, nullptr, nullptr, nullptr, HDIM,
        b_e2, nullptr, 0, out, HDIM, 0);
}

// round 7
// speedup vs baseline: 1.8254x; 1.1466x over previous
#include <cuda_runtime.h>
#include <cuda_bf16.h>
#include <math.h>
#include <stdint.h>

// Problem constants (fixed: ADV=8, GOOD=8, BOX=16, RAMP=8)
#define B_SZ   32768
#define HDIM   256
#define OBS    464
#define N_OTHER 15
#define N_BOX   16
#define N_RAMP  8
#define OFF_OTHER 10
#define OFF_BOX   160
#define OFF_RAMP  368

// Scratch (static device globals — allocation-free). Plain row-major layouts.
__device__ __nv_bfloat16 g_embH[(size_t)B_SZ * 256];
__device__ __nv_bfloat16 g_embL[(size_t)B_SZ * 256];
__device__ float         g_S[(size_t)B_SZ * 768];
__device__ __nv_bfloat16 g_catH[(size_t)B_SZ * 1024];
__device__ __nv_bfloat16 g_catL[(size_t)B_SZ * 1024];
__device__ __nv_bfloat16 g_hH[(size_t)B_SZ * 256];
__device__ __nv_bfloat16 g_hL[(size_t)B_SZ * 256];
// Weights packed [N][K] bf16 hi/lo:
__device__ __nv_bfloat16 g_Bs1H[1024 * 256];   // [corr_other|corr_box|corr_ramp|W_fc]
__device__ __nv_bfloat16 g_Bs1L[1024 * 256];
__device__ __nv_bfloat16 g_Be1H[256 * 1024];
__device__ __nv_bfloat16 g_Be1L[256 * 1024];
__device__ __nv_bfloat16 g_Be2H[256 * 256];
__device__ __nv_bfloat16 g_Be2L[256 * 256];

__device__ __forceinline__ float fast_tanh(float x) {
    float y; asm("tanh.approx.f32 %0, %1;" : "=f"(y) : "f"(x)); return y;
}
__device__ __forceinline__ uint32_t smem_u32(const void* p) {
    uint32_t a;
    asm("{ .reg .u64 t; cvta.to.shared.u64 t, %1; cvt.u32.u64 %0, t; }" : "=r"(a) : "l"(p));
    return a;
}
__device__ __forceinline__ void ldm_x4(uint32_t* r, uint32_t addr) {
    asm volatile("ldmatrix.sync.aligned.m8n8.x4.shared.b16 {%0,%1,%2,%3}, [%4];"
        : "=r"(r[0]), "=r"(r[1]), "=r"(r[2]), "=r"(r[3]) : "r"(addr));
}
__device__ __forceinline__ void mma16816(float* c, const uint32_t* a,
                                         uint32_t b0, uint32_t b1) {
    asm volatile("mma.sync.aligned.m16n8k16.row.col.f32.bf16.bf16.f32 "
        "{%0,%1,%2,%3}, {%4,%5,%6,%7}, {%8,%9}, {%0,%1,%2,%3};"
        : "+f"(c[0]), "+f"(c[1]), "+f"(c[2]), "+f"(c[3])
        : "r"(a[0]), "r"(a[1]), "r"(a[2]), "r"(a[3]), "r"(b0), "r"(b1));
}

// ---------------------------------------------------------------------------
// Weight pack: W [K,256] fp32 -> [N][K] bf16 hi/lo (tiled transpose, coalesced)
// ---------------------------------------------------------------------------
__global__ void pack_weights(const float* __restrict__ W,
                             __nv_bfloat16* __restrict__ oh,
                             __nv_bfloat16* __restrict__ ol, int K) {
    __shared__ float t[32][33];
    int k0 = blockIdx.y * 32, n0 = blockIdx.x * 32;
    int tx = threadIdx.x, ty = threadIdx.y;
    for (int r = ty; r < 32; r += 8)
        t[r][tx] = W[(size_t)(k0 + r) * 256 + n0 + tx];
    __syncthreads();
    for (int r = ty; r < 32; r += 8) {
        int n = n0 + r, k = k0 + tx;
        float x = t[tx][r];
        __nv_bfloat16 h = __float2bfloat16(x);
        float res = x - __bfloat162float(h);
        oh[(size_t)n * K + k] = h;
        ol[(size_t)n * K + k] = __float2bfloat16(res);
    }
}

// ---------------------------------------------------------------------------
// Self embed -> packed hi/lo row-major
// ---------------------------------------------------------------------------
__global__ void self_kernel(const float* __restrict__ inputs,
                            const float* __restrict__ W,
                            const float* __restrict__ b,
                            int rows_per_block) {
    __shared__ float Ws[10 * HDIM];
    __shared__ float bs[HDIM];
    int tid = threadIdx.x;
    for (int i = tid; i < 10 * HDIM; i += blockDim.x) Ws[i] = W[i];
    if (tid < HDIM) bs[tid] = b[tid];
    __syncthreads();

    int row0 = blockIdx.x * rows_per_block;
    for (int r = 0; r < rows_per_block; ++r) {
        int row = row0 + r;
        const float* in = inputs + (size_t)row * OBS;
        float acc = bs[tid];
#pragma unroll
        for (int f = 0; f < 10; ++f) acc += in[f] * Ws[f * HDIM + tid];
        float v = fast_tanh(acc);
        __nv_bfloat16 h = __float2bfloat16(v);
        g_embH[(size_t)row * 256 + tid] = h;
        g_embL[(size_t)row * 256 + tid] = __float2bfloat16(v - __bfloat162float(h));
    }
}

// ---------------------------------------------------------------------------
// Split-bf16 tensor-core GEMM via mma.sync m16n8k16.
// Tile 128x128x32, 8 warps (warp = 32 rows x 64 cols).
// MODE 0: stage1 (N=1024): n0<768 -> raw fp32 S; else gi=tanh(+bias)->cat packed
// MODE 1: e1 -> tanh(+bias) -> h packed
// MODE 2: e2 -> tanh(+bias) -> fp32 out
// ---------------------------------------------------------------------------
#define SPAD 40  // smem row stride (bf16 elems): conflict-free for ldmatrix

template <int MODE>
__global__ __launch_bounds__(256)
void mma_gemm(const __nv_bfloat16* __restrict__ Ahi, const __nv_bfloat16* __restrict__ Alo,
              const __nv_bfloat16* __restrict__ Bhi, const __nv_bfloat16* __restrict__ Blo,
              int K,
              const float* __restrict__ bias,
              float* __restrict__ outF,
              __nv_bfloat16* __restrict__ outHi, __nv_bfloat16* __restrict__ outLo) {
    __shared__ __nv_bfloat16 sAh[128][SPAD], sAl[128][SPAD];
    __shared__ __nv_bfloat16 sBh[128][SPAD], sBl[128][SPAD];

    int tid = threadIdx.x;
    int warp = tid >> 5, lane = tid & 31;
    int wm = warp & 3;        // warp row (32 rows)
    int wn = warp >> 2;       // warp col (64 cols)
    int m0 = blockIdx.y * 128;
    int n0 = blockIdx.x * 128;

    float acc[2][8][4];
#pragma unroll
    for (int mt = 0; mt < 2; ++mt)
#pragma unroll
        for (int nt = 0; nt < 8; ++nt)
#pragma unroll
            for (int i = 0; i < 4; ++i) acc[mt][nt][i] = 0.f;

    // ldmatrix smem addresses (bytes)
    uint32_t aBaseH = smem_u32(&sAh[0][0]), aBaseL = smem_u32(&sAl[0][0]);
    uint32_t bBaseH = smem_u32(&sBh[0][0]), bBaseL = smem_u32(&sBl[0][0]);
    // A: row = wm*32 + mt*16 + (lane&15); halfcol = kt*16 + (lane>>4)*8
    int aRow = wm * 32 + (lane & 15);
    int aColH = (lane >> 4) * 8;
    // B: n = wn*64 + nt2*16 + (lane>>4)*8 + (lane&7); k8 = kt*16 + ((lane>>3)&1)*8
    int bRow = wn * 64 + (lane >> 4) * 8 + (lane & 7);
    int bK8 = ((lane >> 3) & 1) * 8;

    for (int k0 = 0; k0 < K; k0 += 32) {
        // Cooperative load: 4 tiles of 128x32 bf16, uint4 (8 elems) granularity.
#pragma unroll
        for (int u = 0; u < 2; ++u) {
            int i = tid * 2 + u;          // 0..511
            int row = i >> 2, c8 = (i & 3) * 8;
            size_t ga = (size_t)(m0 + row) * K + k0 + c8;
            size_t gb = (size_t)(n0 + row) * K + k0 + c8;
            *(uint4*)&sAh[row][c8] = *(const uint4*)(Ahi + ga);
            *(uint4*)&sAl[row][c8] = *(const uint4*)(Alo + ga);
            *(uint4*)&sBh[row][c8] = *(const uint4*)(Bhi + gb);
            *(uint4*)&sBl[row][c8] = *(const uint4*)(Blo + gb);
        }
        __syncthreads();

#pragma unroll
        for (int kt = 0; kt < 2; ++kt) {
            uint32_t ah[2][4], al[2][4];
#pragma unroll
            for (int mt = 0; mt < 2; ++mt) {
                uint32_t off = (uint32_t)(((aRow + mt * 16) * SPAD + kt * 16 + aColH) * 2);
                ldm_x4(ah[mt], aBaseH + off);
                ldm_x4(al[mt], aBaseL + off);
            }
#pragma unroll
            for (int nt2 = 0; nt2 < 4; ++nt2) {
                uint32_t bh[4], bl[4];
                uint32_t off = (uint32_t)(((bRow + nt2 * 16) * SPAD + kt * 16 + bK8) * 2);
                ldm_x4(bh, bBaseH + off);
                ldm_x4(bl, bBaseL + off);
#pragma unroll
                for (int mt = 0; mt < 2; ++mt) {
                    mma16816(acc[mt][nt2 * 2],     ah[mt], bh[0], bh[1]);
                    mma16816(acc[mt][nt2 * 2 + 1], ah[mt], bh[2], bh[3]);
                    mma16816(acc[mt][nt2 * 2],     ah[mt], bl[0], bl[1]);
                    mma16816(acc[mt][nt2 * 2 + 1], ah[mt], bl[2], bl[3]);
                    mma16816(acc[mt][nt2 * 2],     al[mt], bh[0], bh[1]);
                    mma16816(acc[mt][nt2 * 2 + 1], al[mt], bh[2], bh[3]);
                }
            }
        }
        __syncthreads();
    }

    // Epilogue. Frag (mt, nt): rows m0+wm*32+mt*16+(lane>>2), +8;
    //                          cols n0+wn*64+nt*8+(lane&3)*2, +1
    bool rawS = (MODE == 0) && (n0 < 768);
#pragma unroll
    for (int mt = 0; mt < 2; ++mt) {
#pragma unroll
        for (int nt = 0; nt < 8; ++nt) {
            int r0 = m0 + wm * 32 + mt * 16 + (lane >> 2);
            int col = n0 + wn * 64 + nt * 8 + (lane & 3) * 2;
#pragma unroll
            for (int half = 0; half < 2; ++half) {
                int row = r0 + half * 8;
                float c0 = acc[mt][nt][half * 2], c1 = acc[mt][nt][half * 2 + 1];
                if (rawS) {
                    float2 v = make_float2(c0, c1);
                    *(float2*)(outF + (size_t)row * 768 + col) = v;
                } else if (MODE == 2) {
                    float2 bv = *(const float2*)(bias + col);
                    float2 v = make_float2(fast_tanh(c0 + bv.x), fast_tanh(c1 + bv.y));
                    *(float2*)(outF + (size_t)row * 256 + col) = v;
                } else {
                    int oc = (MODE == 0) ? (col - 768) : col;
                    int ldo = (MODE == 0) ? 1024 : 256;   // cat vs h
                    float2 bv = *(const float2*)(bias + oc);
                    float f0 = fast_tanh(c0 + bv.x);
                    float f1 = fast_tanh(c1 + bv.y);
                    __nv_bfloat16 h0 = __float2bfloat16(f0);
                    __nv_bfloat16 h1 = __float2bfloat16(f1);
                    __nv_bfloat162 hv; hv.x = h0; hv.y = h1;
                    __nv_bfloat162 lv;
                    lv.x = __float2bfloat16(f0 - __bfloat162float(h0));
                    lv.y = __float2bfloat16(f1 - __bfloat162float(h1));
                    int ocol = (MODE == 0) ? oc : col;
                    *(__nv_bfloat162*)(outHi + (size_t)row * ldo + ocol) = hv;
                    *(__nv_bfloat162*)(outLo + (size_t)row * ldo + ocol) = lv;
                }
            }
        }
    }
}

// ---------------------------------------------------------------------------
// Attention pool (warp-pair per row, smem-staged features) -> packed cat hi/lo
// ---------------------------------------------------------------------------
template <int NENT, int FDIM, int IN_OFF, int GOFF, int CAT_OFF>
__global__ __launch_bounds__(256, 2)
void attn_kernel(const float* __restrict__ inputs,
                 const float* __restrict__ S,
                 const float* __restrict__ W,
                 const float* __restrict__ b) {
    constexpr int FT = NENT * FDIM;
    constexpr int FHALF = FT / 2;
    __shared__ float sfeat[4][FT];
    __shared__ float sred[2][2][4];

    int tid = threadIdx.x;
    int warp = tid >> 5, lane = tid & 31;
    int slot = warp >> 1;
    int half = warp & 1;

    float wreg[4][FDIM], breg[4];
#pragma unroll
    for (int j = 0; j < 4; ++j) {
        int h = j * 64 + half * 32 + lane;
        breg[j] = __ldg(b + h);
#pragma unroll
        for (int f = 0; f < FDIM; ++f)
            wreg[j][f] = __ldg(W + f * HDIM + h);
    }

    int step = gridDim.x * 4;
    for (int row0 = blockIdx.x * 4; row0 < B_SZ; row0 += step) {
        int row = row0 + slot;
        {
            const float* rowin = inputs + (size_t)row * OBS + IN_OFF;
            int lo = half * FHALF;
            int hi = half ? FT : FHALF;
            for (int i = lo + lane; i < hi; i += 32)
                sfeat[slot][i] = rowin[i];
        }
        __syncthreads();

        float s[4], acc[4];
#pragma unroll
        for (int j = 0; j < 4; ++j) {
            s[j] = S[(size_t)row * 768 + GOFF + j * 64 + half * 32 + lane];
            acc[j] = 0.f;
        }
        float l = 0.f;

#pragma unroll 1
        for (int n = 0; n < NENT; ++n) {
            const float* feat = &sfeat[slot][n * FDIM];
            float e[4];
#pragma unroll
            for (int j = 0; j < 4; ++j) {
                float a = breg[j];
#pragma unroll
                for (int f = 0; f < FDIM; ++f) a += feat[f] * wreg[j][f];
                e[j] = fast_tanh(a);
            }
            float p = 0.f;
#pragma unroll
            for (int j = 0; j < 4; ++j) p += s[j] * e[j];
#pragma unroll
            for (int off = 16; off > 0; off >>= 1)
                p += __shfl_xor_sync(0xFFFFFFFFu, p, off);
            if (lane == 0) sred[n & 1][half][slot] = p;
            __syncthreads();
            float bp = sred[n & 1][0][slot] + sred[n & 1][1][slot];
            float w = __expf(bp);
            l += w;
#pragma unroll
            for (int j = 0; j < 4; ++j) acc[j] += w * e[j];
        }

        float inv = 1.f / l;
#pragma unroll
        for (int j = 0; j < 4; ++j) {
            float f = acc[j] * inv;
            int col = CAT_OFF + j * 64 + half * 32 + lane;
            __nv_bfloat16 h = __float2bfloat16(f);
            g_catH[(size_t)row * 1024 + col] = h;
            g_catL[(size_t)row * 1024 + col] = __float2bfloat16(f - __bfloat162float(h));
        }
    }
}

// ---------------------------------------------------------------------------
extern "C" void kernel_launch(void* const* d_in, const int* in_sizes, int n_in,
                              void* d_out, int out_size) {
    const float* inputs     = (const float*)d_in[0];
    const float* W_self     = (const float*)d_in[1];
    const float* b_self     = (const float*)d_in[2];
    const float* W_other    = (const float*)d_in[3];
    const float* b_other    = (const float*)d_in[4];
    const float* W_box      = (const float*)d_in[5];
    const float* b_box      = (const float*)d_in[6];
    const float* W_ramp     = (const float*)d_in[7];
    const float* b_ramp     = (const float*)d_in[8];
    const float* corr_other = (const float*)d_in[9];
    const float* corr_box   = (const float*)d_in[10];
    const float* corr_ramp  = (const float*)d_in[11];
    const float* W_fc       = (const float*)d_in[12];
    const float* b_fc       = (const float*)d_in[13];
    const float* W_e1       = (const float*)d_in[14];
    const float* b_e1       = (const float*)d_in[15];
    const float* W_e2       = (const float*)d_in[16];
    const float* b_e2       = (const float*)d_in[17];
    float* out = (float*)d_out;

    __nv_bfloat16 *embH, *embL, *catH, *catL, *hH, *hL;
    __nv_bfloat16 *Bs1H, *Bs1L, *Be1H, *Be1L, *Be2H, *Be2L;
    float* S;
    cudaGetSymbolAddress((void**)&embH, g_embH);
    cudaGetSymbolAddress((void**)&embL, g_embL);
    cudaGetSymbolAddress((void**)&S,    g_S);
    cudaGetSymbolAddress((void**)&catH, g_catH);
    cudaGetSymbolAddress((void**)&catL, g_catL);
    cudaGetSymbolAddress((void**)&hH,   g_hH);
    cudaGetSymbolAddress((void**)&hL,   g_hL);
    cudaGetSymbolAddress((void**)&Bs1H, g_Bs1H);
    cudaGetSymbolAddress((void**)&Bs1L, g_Bs1L);
    cudaGetSymbolAddress((void**)&Be1H, g_Be1H);
    cudaGetSymbolAddress((void**)&Be1L, g_Be1L);
    cudaGetSymbolAddress((void**)&Be2H, g_Be2H);
    cudaGetSymbolAddress((void**)&Be2L, g_Be2L);

    dim3 pb(32, 8);
    // stage1 fused B: rows [0,256)=corr_other, [256,512)=corr_box, [512,768)=corr_ramp, [768,1024)=W_fc
    pack_weights<<<dim3(8, 8),  pb>>>(corr_other, Bs1H + 0 * 256 * 256, Bs1L + 0 * 256 * 256, 256);
    pack_weights<<<dim3(8, 8),  pb>>>(corr_box,   Bs1H + 1 * 256 * 256, Bs1L + 1 * 256 * 256, 256);
    pack_weights<<<dim3(8, 8),  pb>>>(corr_ramp,  Bs1H + 2 * 256 * 256, Bs1L + 2 * 256 * 256, 256);
    pack_weights<<<dim3(8, 8),  pb>>>(W_fc,       Bs1H + 3 * 256 * 256, Bs1L + 3 * 256 * 256, 256);
    pack_weights<<<dim3(8, 32), pb>>>(W_e1, Be1H, Be1L, 1024);
    pack_weights<<<dim3(8, 8),  pb>>>(W_e2, Be2H, Be2L, 256);

    const int RPB = 32;
    self_kernel<<<B_SZ / RPB, 256>>>(inputs, W_self, b_self, RPB);

    // Stage1: emb @ fused-B (N=1024, K=256) -> S fp32 (cols<768) + gi packed (cols>=768)
    mma_gemm<0><<<dim3(8, B_SZ / 128), 256>>>(
        embH, embL, Bs1H, Bs1L, 256, b_fc, S, catH, catL);

    const int ATTN_BLOCKS = 2048;
    attn_kernel<N_OTHER, 10, OFF_OTHER, 0,   1 * HDIM><<<ATTN_BLOCKS, 256>>>(inputs, S, W_other, b_other);
    attn_kernel<N_BOX,   13, OFF_BOX,   256, 2 * HDIM><<<ATTN_BLOCKS, 256>>>(inputs, S, W_box, b_box);
    attn_kernel<N_RAMP,  12, OFF_RAMP,  512, 3 * HDIM><<<ATTN_BLOCKS, 256>>>(inputs, S, W_ramp, b_ramp);

    // e1: h = tanh(cat @ W_e1 + b_e1)  (N=256, K=1024) -> packed h
    mma_gemm<1><<<dim3(2, B_SZ / 128), 256>>>(
        catH, catL, Be1H, Be1L, 1024, b_e1, nullptr, hH, hL);
    // e2: out = tanh(h @ W_e2 + b_e2)  (N=256, K=256) -> fp32
    mma_gemm<2><<<dim3(2, B_SZ / 128), 256>>>(
        hH, hL, Be2H, Be2L, 256, b_e2, out, nullptr, nullptr);
}

// round 8
// speedup vs baseline: 2.4191x; 1.3252x over previous
#include <cuda_runtime.h>
#include <cuda_bf16.h>
#include <math.h>
#include <stdint.h>

// Problem constants (fixed: ADV=8, GOOD=8, BOX=16, RAMP=8)
#define B_SZ   32768
#define HDIM   256
#define OBS    464
#define N_OTHER 15
#define N_BOX   16
#define N_RAMP  8
#define OFF_OTHER 10
#define OFF_BOX   160
#define OFF_RAMP  368

// Scratch (static device globals — allocation-free). Plain row-major layouts.
__device__ __nv_bfloat16 g_embH[(size_t)B_SZ * 256];
__device__ __nv_bfloat16 g_embL[(size_t)B_SZ * 256];
__device__ float         g_S[(size_t)B_SZ * 768];
__device__ __nv_bfloat16 g_catH[(size_t)B_SZ * 1024];
__device__ __nv_bfloat16 g_catL[(size_t)B_SZ * 1024];
__device__ __nv_bfloat16 g_hH[(size_t)B_SZ * 256];
__device__ __nv_bfloat16 g_hL[(size_t)B_SZ * 256];
// Weights packed [N][K] bf16 hi/lo:
__device__ __nv_bfloat16 g_Bs1H[1024 * 256];   // [corr_other|corr_box|corr_ramp|W_fc]
__device__ __nv_bfloat16 g_Bs1L[1024 * 256];
__device__ __nv_bfloat16 g_Be1H[256 * 1024];
__device__ __nv_bfloat16 g_Be1L[256 * 1024];
__device__ __nv_bfloat16 g_Be2H[256 * 256];
__device__ __nv_bfloat16 g_Be2L[256 * 256];

__device__ __forceinline__ float fast_tanh(float x) {
    float y; asm("tanh.approx.f32 %0, %1;" : "=f"(y) : "f"(x)); return y;
}
__device__ __forceinline__ uint32_t smem_u32(const void* p) {
    uint32_t a;
    asm("{ .reg .u64 t; cvta.to.shared.u64 t, %1; cvt.u32.u64 %0, t; }" : "=r"(a) : "l"(p));
    return a;
}
__device__ __forceinline__ void ldm_x4(uint32_t* r, uint32_t addr) {
    asm volatile("ldmatrix.sync.aligned.m8n8.x4.shared.b16 {%0,%1,%2,%3}, [%4];"
        : "=r"(r[0]), "=r"(r[1]), "=r"(r[2]), "=r"(r[3]) : "r"(addr));
}
__device__ __forceinline__ void mma16816(float* c, const uint32_t* a,
                                         uint32_t b0, uint32_t b1) {
    asm volatile("mma.sync.aligned.m16n8k16.row.col.f32.bf16.bf16.f32 "
        "{%0,%1,%2,%3}, {%4,%5,%6,%7}, {%8,%9}, {%0,%1,%2,%3};"
        : "+f"(c[0]), "+f"(c[1]), "+f"(c[2]), "+f"(c[3])
        : "r"(a[0]), "r"(a[1]), "r"(a[2]), "r"(a[3]), "r"(b0), "r"(b1));
}
__device__ __forceinline__ void cpa16(uint32_t s, const void* g) {
    asm volatile("cp.async.cg.shared.global [%0], [%1], 16;" :: "r"(s), "l"(g));
}
#define CPA_COMMIT() asm volatile("cp.async.commit_group;" ::: "memory")
#define CPA_WAIT1()  asm volatile("cp.async.wait_group 1;" ::: "memory")
#define CPA_WAIT0()  asm volatile("cp.async.wait_group 0;" ::: "memory")

// ---------------------------------------------------------------------------
// One launch packs all 6 weight matrices: fp32 [K,256] -> [N=256][K] bf16 hi/lo
// ---------------------------------------------------------------------------
struct PackArgs {
    const float* W[6];
    __nv_bfloat16* oh[6];
    __nv_bfloat16* ol[6];
    int K[6];
    int start[7];
};
__global__ void pack_all(PackArgs pa) {
    __shared__ float t[32][33];
    int bx = blockIdx.x;
    int job = 0;
    while (bx >= pa.start[job + 1]) ++job;
    int local = bx - pa.start[job];
    int n0 = (local & 7) * 32;
    int k0 = (local >> 3) * 32;
    int K = pa.K[job];
    const float* W = pa.W[job];
    __nv_bfloat16* oh = pa.oh[job];
    __nv_bfloat16* ol = pa.ol[job];
    int tx = threadIdx.x, ty = threadIdx.y;
    for (int r = ty; r < 32; r += 8)
        t[r][tx] = W[(size_t)(k0 + r) * 256 + n0 + tx];
    __syncthreads();
    for (int r = ty; r < 32; r += 8) {
        int n = n0 + r, k = k0 + tx;
        float x = t[tx][r];
        __nv_bfloat16 h = __float2bfloat16(x);
        oh[(size_t)n * K + k] = h;
        ol[(size_t)n * K + k] = __float2bfloat16(x - __bfloat162float(h));
    }
}

// ---------------------------------------------------------------------------
// Self embed -> packed hi/lo row-major
// ---------------------------------------------------------------------------
__global__ void self_kernel(const float* __restrict__ inputs,
                            const float* __restrict__ W,
                            const float* __restrict__ b,
                            int rows_per_block) {
    __shared__ float Ws[10 * HDIM];
    __shared__ float bs[HDIM];
    int tid = threadIdx.x;
    for (int i = tid; i < 10 * HDIM; i += blockDim.x) Ws[i] = W[i];
    if (tid < HDIM) bs[tid] = b[tid];
    __syncthreads();

    int row0 = blockIdx.x * rows_per_block;
    for (int r = 0; r < rows_per_block; ++r) {
        int row = row0 + r;
        const float* in = inputs + (size_t)row * OBS;
        float acc = bs[tid];
#pragma unroll
        for (int f = 0; f < 10; ++f) acc += in[f] * Ws[f * HDIM + tid];
        float v = fast_tanh(acc);
        __nv_bfloat16 h = __float2bfloat16(v);
        g_embH[(size_t)row * 256 + tid] = h;
        g_embL[(size_t)row * 256 + tid] = __float2bfloat16(v - __bfloat162float(h));
    }
}

// ---------------------------------------------------------------------------
// Split-bf16 mma.sync GEMM, tile 128x128x32, 8 warps, cp.async 2-stage pipeline.
// MODE 0: stage1 (N=1024): n0<768 -> raw fp32 S; else gi=tanh(+bias)->cat packed
// MODE 1: e1 -> tanh(+bias) -> h packed
// MODE 2: e2 -> tanh(+bias) -> fp32 out
// ---------------------------------------------------------------------------
#define SPAD 40                      // bf16 elems per smem row (80B)
#define TILE_B 10240                 // 128*SPAD*2 bytes per tile
#define STAGE_B (4 * TILE_B)         // AH, AL, BH, BL
#define GEMM_SMEM (2 * STAGE_B)      // 81920 B

template <int MODE>
__global__ __launch_bounds__(256)
void mma_gemm(const __nv_bfloat16* __restrict__ Ahi, const __nv_bfloat16* __restrict__ Alo,
              const __nv_bfloat16* __restrict__ Bhi, const __nv_bfloat16* __restrict__ Blo,
              int K,
              const float* __restrict__ bias,
              float* __restrict__ outF,
              __nv_bfloat16* __restrict__ outHi, __nv_bfloat16* __restrict__ outLo) {
    extern __shared__ char smem[];
    uint32_t sb = smem_u32(smem);

    int tid = threadIdx.x;
    int warp = tid >> 5, lane = tid & 31;
    int wm = warp & 3;        // warp row (32 rows)
    int wn = warp >> 2;       // warp col (64 cols)
    int m0 = blockIdx.y * 128;
    int n0 = blockIdx.x * 128;

    float acc[2][8][4];
#pragma unroll
    for (int mt = 0; mt < 2; ++mt)
#pragma unroll
        for (int nt = 0; nt < 8; ++nt)
#pragma unroll
            for (int i = 0; i < 4; ++i) acc[mt][nt][i] = 0.f;

    // ldmatrix lane addressing (element coords)
    int aRow = wm * 32 + (lane & 15);
    int aColH = (lane >> 4) * 8;
    int bRow = wn * 64 + (lane >> 4) * 8 + (lane & 7);
    int bK8 = ((lane >> 3) & 1) * 8;

    // loader lane mapping
    int lrow = tid >> 1;                   // 0..127
    int lc8a = ((tid & 1) * 2) * 8;        // 0 or 16
    int lc8b = ((tid & 1) * 2 + 1) * 8;    // 8 or 24

    auto load_tiles = [&](int t) {
        uint32_t stb = sb + (uint32_t)(t & 1) * STAGE_B;
        size_t ka = (size_t)(m0 + lrow) * K + t * 32;
        size_t kb = (size_t)(n0 + lrow) * K + t * 32;
        uint32_t so = (uint32_t)(lrow * (SPAD * 2));
        cpa16(stb + so + lc8a * 2,            Ahi + ka + lc8a);
        cpa16(stb + so + lc8b * 2,            Ahi + ka + lc8b);
        cpa16(stb + TILE_B + so + lc8a * 2,   Alo + ka + lc8a);
        cpa16(stb + TILE_B + so + lc8b * 2,   Alo + ka + lc8b);
        cpa16(stb + 2*TILE_B + so + lc8a * 2, Bhi + kb + lc8a);
        cpa16(stb + 2*TILE_B + so + lc8b * 2, Bhi + kb + lc8b);
        cpa16(stb + 3*TILE_B + so + lc8a * 2, Blo + kb + lc8a);
        cpa16(stb + 3*TILE_B + so + lc8b * 2, Blo + kb + lc8b);
        CPA_COMMIT();
    };

    int nt = K >> 5;
    load_tiles(0);
    for (int t = 0; t < nt; ++t) {
        if (t + 1 < nt) { load_tiles(t + 1); CPA_WAIT1(); }
        else            { CPA_WAIT0(); }
        __syncthreads();

        uint32_t stb = sb + (uint32_t)(t & 1) * STAGE_B;
        uint32_t aBaseH = stb, aBaseL = stb + TILE_B;
        uint32_t bBaseH = stb + 2 * TILE_B, bBaseL = stb + 3 * TILE_B;

#pragma unroll
        for (int kt = 0; kt < 2; ++kt) {
            uint32_t ah[2][4], al[2][4];
#pragma unroll
            for (int mt = 0; mt < 2; ++mt) {
                uint32_t off = (uint32_t)(((aRow + mt * 16) * SPAD + kt * 16 + aColH) * 2);
                ldm_x4(ah[mt], aBaseH + off);
                ldm_x4(al[mt], aBaseL + off);
            }
#pragma unroll
            for (int nt2 = 0; nt2 < 4; ++nt2) {
                uint32_t bh[4], bl[4];
                uint32_t off = (uint32_t)(((bRow + nt2 * 16) * SPAD + kt * 16 + bK8) * 2);
                ldm_x4(bh, bBaseH + off);
                ldm_x4(bl, bBaseL + off);
#pragma unroll
                for (int mt = 0; mt < 2; ++mt) {
                    mma16816(acc[mt][nt2 * 2],     ah[mt], bh[0], bh[1]);
                    mma16816(acc[mt][nt2 * 2 + 1], ah[mt], bh[2], bh[3]);
                    mma16816(acc[mt][nt2 * 2],     ah[mt], bl[0], bl[1]);
                    mma16816(acc[mt][nt2 * 2 + 1], ah[mt], bl[2], bl[3]);
                    mma16816(acc[mt][nt2 * 2],     al[mt], bh[0], bh[1]);
                    mma16816(acc[mt][nt2 * 2 + 1], al[mt], bh[2], bh[3]);
                }
            }
        }
        __syncthreads();
    }

    // Epilogue. Frag (mt, nt): rows m0+wm*32+mt*16+(lane>>2), +8;
    //                          cols n0+wn*64+nt*8+(lane&3)*2, +1
    bool rawS = (MODE == 0) && (n0 < 768);
#pragma unroll
    for (int mt = 0; mt < 2; ++mt) {
#pragma unroll
        for (int nt = 0; nt < 8; ++nt) {
            int r0 = m0 + wm * 32 + mt * 16 + (lane >> 2);
            int col = n0 + wn * 64 + nt * 8 + (lane & 3) * 2;
#pragma unroll
            for (int half = 0; half < 2; ++half) {
                int row = r0 + half * 8;
                float c0 = acc[mt][nt][half * 2], c1 = acc[mt][nt][half * 2 + 1];
                if (rawS) {
                    *(float2*)(outF + (size_t)row * 768 + col) = make_float2(c0, c1);
                } else if (MODE == 2) {
                    float2 bv = *(const float2*)(bias + col);
                    *(float2*)(outF + (size_t)row * 256 + col) =
                        make_float2(fast_tanh(c0 + bv.x), fast_tanh(c1 + bv.y));
                } else {
                    int oc = (MODE == 0) ? (col - 768) : col;
                    int ldo = (MODE == 0) ? 1024 : 256;
                    float2 bv = *(const float2*)(bias + oc);
                    float f0 = fast_tanh(c0 + bv.x);
                    float f1 = fast_tanh(c1 + bv.y);
                    __nv_bfloat16 h0 = __float2bfloat16(f0);
                    __nv_bfloat16 h1 = __float2bfloat16(f1);
                    __nv_bfloat162 hv; hv.x = h0; hv.y = h1;
                    __nv_bfloat162 lv;
                    lv.x = __float2bfloat16(f0 - __bfloat162float(h0));
                    lv.y = __float2bfloat16(f1 - __bfloat162float(h1));
                    int ocol = (MODE == 0) ? oc : col;
                    *(__nv_bfloat162*)(outHi + (size_t)row * ldo + ocol) = hv;
                    *(__nv_bfloat162*)(outLo + (size_t)row * ldo + ocol) = lv;
                }
            }
        }
    }
}

// ---------------------------------------------------------------------------
// Unified attention: 3 groups in one launch (block-range dispatch).
// Warp-pair per row; entity PAIR batching halves barrier rounds.
// ---------------------------------------------------------------------------
template <int NENT, int FDIM, int IN_OFF, int GOFF, int CAT_OFF>
__device__ __forceinline__
void attn_body(const float* __restrict__ inputs, const float* __restrict__ S,
               const float* __restrict__ W, const float* __restrict__ bias,
               int bid, float (*sfeat)[208], float* sred) {
    constexpr int FT = NENT * FDIM;
    constexpr int FHALF = FT / 2;
    constexpr int NPAIR = NENT / 2;

    int tid = threadIdx.x;
    int warp = tid >> 5, lane = tid & 31;
    int slot = warp >> 1;
    int half = warp & 1;

    float wreg[4][FDIM], breg[4];
#pragma unroll
    for (int j = 0; j < 4; ++j) {
        int h = j * 64 + half * 32 + lane;
        breg[j] = __ldg(bias + h);
#pragma unroll
        for (int f = 0; f < FDIM; ++f)
            wreg[j][f] = __ldg(W + f * HDIM + h);
    }

    // sred index: ((pp*2 + which)*2 + half)*4 + slot
    for (int row0 = bid * 4; row0 < B_SZ; row0 += 4096) {
        int row = row0 + slot;
        {
            const float* rowin = inputs + (size_t)row * OBS + IN_OFF;
            int lo = half * FHALF;
            int hi = half ? FT : FHALF;
            for (int i = lo + lane; i < hi; i += 32)
                sfeat[slot][i] = rowin[i];
        }
        __syncthreads();

        float s[4], acc[4];
#pragma unroll
        for (int j = 0; j < 4; ++j) {
            s[j] = S[(size_t)row * 768 + GOFF + j * 64 + half * 32 + lane];
            acc[j] = 0.f;
        }
        float l = 0.f;

#pragma unroll 1
        for (int np = 0; np < NPAIR; ++np) {
            int n = np * 2;
            const float* f0 = &sfeat[slot][n * FDIM];
            const float* f1 = f0 + FDIM;
            float e0[4], e1[4];
#pragma unroll
            for (int j = 0; j < 4; ++j) {
                float a0 = breg[j], a1 = breg[j];
#pragma unroll
                for (int f = 0; f < FDIM; ++f) {
                    a0 += f0[f] * wreg[j][f];
                    a1 += f1[f] * wreg[j][f];
                }
                e0[j] = fast_tanh(a0);
                e1[j] = fast_tanh(a1);
            }
            float p0 = 0.f, p1 = 0.f;
#pragma unroll
            for (int j = 0; j < 4; ++j) { p0 += s[j] * e0[j]; p1 += s[j] * e1[j]; }
#pragma unroll
            for (int off = 16; off > 0; off >>= 1) {
                p0 += __shfl_xor_sync(0xFFFFFFFFu, p0, off);
                p1 += __shfl_xor_sync(0xFFFFFFFFu, p1, off);
            }
            int pp = np & 1;
            if (lane == 0) {
                sred[((pp * 2 + 0) * 2 + half) * 4 + slot] = p0;
                sred[((pp * 2 + 1) * 2 + half) * 4 + slot] = p1;
            }
            __syncthreads();
            float bp0 = sred[((pp * 2 + 0) * 2 + 0) * 4 + slot] +
                        sred[((pp * 2 + 0) * 2 + 1) * 4 + slot];
            float bp1 = sred[((pp * 2 + 1) * 2 + 0) * 4 + slot] +
                        sred[((pp * 2 + 1) * 2 + 1) * 4 + slot];
            float w0 = __expf(bp0), w1 = __expf(bp1);
            l += w0 + w1;
#pragma unroll
            for (int j = 0; j < 4; ++j) acc[j] += w0 * e0[j] + w1 * e1[j];
        }

        if (NENT & 1) {  // tail entity
            int n = NENT - 1;
            const float* ft = &sfeat[slot][n * FDIM];
            float e0[4];
#pragma unroll
            for (int j = 0; j < 4; ++j) {
                float a = breg[j];
#pragma unroll
                for (int f = 0; f < FDIM; ++f) a += ft[f] * wreg[j][f];
                e0[j] = fast_tanh(a);
            }
            float p0 = 0.f;
#pragma unroll
            for (int j = 0; j < 4; ++j) p0 += s[j] * e0[j];
#pragma unroll
            for (int off = 16; off > 0; off >>= 1)
                p0 += __shfl_xor_sync(0xFFFFFFFFu, p0, off);
            int pp = NPAIR & 1;
            if (lane == 0) sred[((pp * 2 + 0) * 2 + half) * 4 + slot] = p0;
            __syncthreads();
            float bp0 = sred[((pp * 2 + 0) * 2 + 0) * 4 + slot] +
                        sred[((pp * 2 + 0) * 2 + 1) * 4 + slot];
            float w0 = __expf(bp0);
            l += w0;
#pragma unroll
            for (int j = 0; j < 4; ++j) acc[j] += w0 * e0[j];
        }

        float inv = 1.f / l;
#pragma unroll
        for (int j = 0; j < 4; ++j) {
            float f = acc[j] * inv;
            int col = CAT_OFF + j * 64 + half * 32 + lane;
            __nv_bfloat16 h = __float2bfloat16(f);
            g_catH[(size_t)row * 1024 + col] = h;
            g_catL[(size_t)row * 1024 + col] = __float2bfloat16(f - __bfloat162float(h));
        }
        __syncthreads();   // protect sfeat/sred reuse across row iterations
    }
}

__global__ __launch_bounds__(256, 2)
void attn_all(const float* __restrict__ inputs, const float* __restrict__ S,
              const float* __restrict__ Wo, const float* __restrict__ bo,
              const float* __restrict__ Wb, const float* __restrict__ bb,
              const float* __restrict__ Wr, const float* __restrict__ br) {
    __shared__ float sfeat[4][208];
    __shared__ float sred[32];
    int grp = blockIdx.x >> 10;
    int bid = blockIdx.x & 1023;
    if (grp == 0)
        attn_body<N_OTHER, 10, OFF_OTHER, 0,   256>(inputs, S, Wo, bo, bid, sfeat, sred);
    else if (grp == 1)
        attn_body<N_BOX,   13, OFF_BOX,   256, 512>(inputs, S, Wb, bb, bid, sfeat, sred);
    else
        attn_body<N_RAMP,  12, OFF_RAMP,  512, 768>(inputs, S, Wr, br, bid, sfeat, sred);
}

// ---------------------------------------------------------------------------
extern "C" void kernel_launch(void* const* d_in, const int* in_sizes, int n_in,
                              void* d_out, int out_size) {
    const float* inputs     = (const float*)d_in[0];
    const float* W_self     = (const float*)d_in[1];
    const float* b_self     = (const float*)d_in[2];
    const float* W_other    = (const float*)d_in[3];
    const float* b_other    = (const float*)d_in[4];
    const float* W_box      = (const float*)d_in[5];
    const float* b_box      = (const float*)d_in[6];
    const float* W_ramp     = (const float*)d_in[7];
    const float* b_ramp     = (const float*)d_in[8];
    const float* corr_other = (const float*)d_in[9];
    const float* corr_box   = (const float*)d_in[10];
    const float* corr_ramp  = (const float*)d_in[11];
    const float* W_fc       = (const float*)d_in[12];
    const float* b_fc       = (const float*)d_in[13];
    const float* W_e1       = (const float*)d_in[14];
    const float* b_e1       = (const float*)d_in[15];
    const float* W_e2       = (const float*)d_in[16];
    const float* b_e2       = (const float*)d_in[17];
    float* out = (float*)d_out;

    __nv_bfloat16 *embH, *embL, *catH, *catL, *hH, *hL;
    __nv_bfloat16 *Bs1H, *Bs1L, *Be1H, *Be1L, *Be2H, *Be2L;
    float* S;
    cudaGetSymbolAddress((void**)&embH, g_embH);
    cudaGetSymbolAddress((void**)&embL, g_embL);
    cudaGetSymbolAddress((void**)&S,    g_S);
    cudaGetSymbolAddress((void**)&catH, g_catH);
    cudaGetSymbolAddress((void**)&catL, g_catL);
    cudaGetSymbolAddress((void**)&hH,   g_hH);
    cudaGetSymbolAddress((void**)&hL,   g_hL);
    cudaGetSymbolAddress((void**)&Bs1H, g_Bs1H);
    cudaGetSymbolAddress((void**)&Bs1L, g_Bs1L);
    cudaGetSymbolAddress((void**)&Be1H, g_Be1H);
    cudaGetSymbolAddress((void**)&Be1L, g_Be1L);
    cudaGetSymbolAddress((void**)&Be2H, g_Be2H);
    cudaGetSymbolAddress((void**)&Be2L, g_Be2L);

    cudaFuncSetAttribute(mma_gemm<0>, cudaFuncAttributeMaxDynamicSharedMemorySize, GEMM_SMEM);
    cudaFuncSetAttribute(mma_gemm<1>, cudaFuncAttributeMaxDynamicSharedMemorySize, GEMM_SMEM);
    cudaFuncSetAttribute(mma_gemm<2>, cudaFuncAttributeMaxDynamicSharedMemorySize, GEMM_SMEM);

    // One launch: pack all 6 weight matrices.
    PackArgs pa;
    pa.W[0] = corr_other; pa.oh[0] = Bs1H + 0 * 65536; pa.ol[0] = Bs1L + 0 * 65536; pa.K[0] = 256;
    pa.W[1] = corr_box;   pa.oh[1] = Bs1H + 1 * 65536; pa.ol[1] = Bs1L + 1 * 65536; pa.K[1] = 256;
    pa.W[2] = corr_ramp;  pa.oh[2] = Bs1H + 2 * 65536; pa.ol[2] = Bs1L + 2 * 65536; pa.K[2] = 256;
    pa.W[3] = W_fc;       pa.oh[3] = Bs1H + 3 * 65536; pa.ol[3] = Bs1L + 3 * 65536; pa.K[3] = 256;
    pa.W[4] = W_e1;       pa.oh[4] = Be1H;             pa.ol[4] = Be1L;             pa.K[4] = 1024;
    pa.W[5] = W_e2;       pa.oh[5] = Be2H;             pa.ol[5] = Be2L;             pa.K[5] = 256;
    pa.start[0] = 0;   pa.start[1] = 64;  pa.start[2] = 128; pa.start[3] = 192;
    pa.start[4] = 256; pa.start[5] = 512; pa.start[6] = 576;
    pack_all<<<576, dim3(32, 8)>>>(pa);

    const int RPB = 32;
    self_kernel<<<B_SZ / RPB, 256>>>(inputs, W_self, b_self, RPB);

    // Stage1: emb @ fused-B (N=1024, K=256) -> S fp32 (cols<768) + gi packed
    mma_gemm<0><<<dim3(8, B_SZ / 128), 256, GEMM_SMEM>>>(
        embH, embL, Bs1H, Bs1L, 256, b_fc, S, catH, catL);

    // Unified attention (3 groups x 1024 blocks)
    attn_all<<<3072, 256>>>(inputs, S, W_other, b_other, W_box, b_box, W_ramp, b_ramp);

    // e1: h = tanh(cat @ W_e1 + b_e1)  (N=256, K=1024)
    mma_gemm<1><<<dim3(2, B_SZ / 128), 256, GEMM_SMEM>>>(
        catH, catL, Be1H, Be1L, 1024, b_e1, nullptr, hH, hL);
    // e2: out = tanh(h @ W_e2 + b_e2)  (N=256, K=256)
    mma_gemm<2><<<dim3(2, B_SZ / 128), 256, GEMM_SMEM>>>(
        hH, hL, Be2H, Be2L, 256, b_e2, out, nullptr, nullptr);
}